// round 8
// baseline (speedup 1.0000x reference)
#include <cuda_runtime.h>
#include <cuda_bf16.h>
#include <cstdint>

// ---------------------------------------------------------------------------
// Problem constants
// ---------------------------------------------------------------------------
#define BATCH   2
#define SEQ     2048
#define DMODEL  1024
#define NHEAD   16
#define DK      64
#define BH      (BATCH * NHEAD)              // 32
#define TOKENS  (BATCH * SEQ)                // 4096
#define OUT0    (TOKENS * DMODEL)            // 4,194,304
#define ATTN_N  ((long)BH * SEQ * SEQ)       // 134,217,728
#define OUT_TOTAL (OUT0 + ATTN_N)

// ---------------------------------------------------------------------------
// Scratch (static device arrays; no cudaMalloc anywhere)
// ---------------------------------------------------------------------------
__device__ __nv_bfloat16 g_Qh[TOKENS * DMODEL], g_Ql[TOKENS * DMODEL];
__device__ __nv_bfloat16 g_Kh[TOKENS * DMODEL], g_Kl[TOKENS * DMODEL];
__device__ __nv_bfloat16 g_Vh[TOKENS * DMODEL], g_Vl[TOKENS * DMODEL];
__device__ __nv_bfloat16 g_Wqh[DMODEL * DMODEL], g_Wql[DMODEL * DMODEL];
__device__ __nv_bfloat16 g_Wkh[DMODEL * DMODEL], g_Wkl[DMODEL * DMODEL];
__device__ __nv_bfloat16 g_Wvh[DMODEL * DMODEL], g_Wvl[DMODEL * DMODEL];
__device__ __nv_bfloat16 g_Woh[DMODEL * DMODEL], g_Wol[DMODEL * DMODEL];
__device__ __nv_bfloat16 g_qh[TOKENS * DMODEL], g_ql[TOKENS * DMODEL];   // [B,S,H*64]
__device__ __nv_bfloat16 g_kh[TOKENS * DMODEL], g_kl[TOKENS * DMODEL];   // [B,S,H*64]
__device__ __nv_bfloat16 g_vth[BH * DK * SEQ], g_vtl[BH * DK * SEQ];     // [BH,64,S]
__device__ __nv_bfloat16 g_ch[TOKENS * DMODEL], g_cl[TOKENS * DMODEL];   // ctx [B,S,D]
__device__ float g_attn[ATTN_N];                 // fallback if d_out lacks attn

// ---------------------------------------------------------------------------
// Helpers
// ---------------------------------------------------------------------------
__device__ __forceinline__ uint32_t smem_u32(const void* p) {
    uint32_t a;
    asm("{ .reg .u64 t; cvta.to.shared.u64 t, %1; cvt.u32.u64 %0, t; }"
        : "=r"(a) : "l"(p));
    return a;
}
#define SWZ(off) ((off) ^ (((off) >> 3) & 0x70))

__device__ __forceinline__ void ldsm_x4(uint32_t& r0, uint32_t& r1,
                                        uint32_t& r2, uint32_t& r3, uint32_t a) {
    asm volatile("ldmatrix.sync.aligned.m8n8.x4.shared.b16 {%0,%1,%2,%3}, [%4];"
                 : "=r"(r0), "=r"(r1), "=r"(r2), "=r"(r3) : "r"(a));
}
__device__ __forceinline__ void mma16816(float* c, const uint32_t* a,
                                         uint32_t b0, uint32_t b1) {
    asm volatile(
        "mma.sync.aligned.m16n8k16.row.col.f32.bf16.bf16.f32 "
        "{%0,%1,%2,%3}, {%4,%5,%6,%7}, {%8,%9}, {%0,%1,%2,%3};"
        : "+f"(c[0]), "+f"(c[1]), "+f"(c[2]), "+f"(c[3])
        : "r"(a[0]), "r"(a[1]), "r"(a[2]), "r"(a[3]), "r"(b0), "r"(b1));
}
__device__ __forceinline__ void cp16(uint32_t dst, const void* src) {
    asm volatile("cp.async.cg.shared.global [%0], [%1], 16;"
                 :: "r"(dst), "l"(src) : "memory");
}
#define CP_COMMIT() asm volatile("cp.async.commit_group;" ::: "memory")
#define CP_WAIT1()  asm volatile("cp.async.wait_group 1;" ::: "memory")
#define CP_WAIT0()  asm volatile("cp.async.wait_group 0;" ::: "memory")

// pack two fp32 -> bf16x2 register (first arg in low half)
__device__ __forceinline__ uint32_t pack_bf16(float lo, float hi) {
    uint32_t r;
    asm("cvt.rn.bf16x2.f32 %0, %1, %2;" : "=r"(r) : "f"(hi), "f"(lo));
    return r;
}
__device__ __forceinline__ float bf16lo_f(uint32_t r) {
    return __bfloat162float(__ushort_as_bfloat16((unsigned short)(r & 0xffffu)));
}
__device__ __forceinline__ float bf16hi_f(uint32_t r) {
    return __bfloat162float(__ushort_as_bfloat16((unsigned short)(r >> 16)));
}

// ---------------------------------------------------------------------------
// One-launch fp32 -> bf16 hi/lo split over all 7 inputs (grid.y = segment)
// ---------------------------------------------------------------------------
struct SplitArgs {
    const float* x[7];
    __nv_bfloat16* h[7];
    __nv_bfloat16* l[7];
    int n4[7];                 // float4 group count per segment
};

__global__ void __launch_bounds__(256)
split_all(SplitArgs a)
{
    const int seg = blockIdx.y;
    const int i = blockIdx.x * 256 + threadIdx.x;
    if (i >= a.n4[seg]) return;
    float4 v = ((const float4*)a.x[seg])[i];
    __nv_bfloat16 h0 = __float2bfloat16(v.x), h1 = __float2bfloat16(v.y);
    __nv_bfloat16 h2 = __float2bfloat16(v.z), h3 = __float2bfloat16(v.w);
    float l0 = v.x - __bfloat162float(h0), l1 = v.y - __bfloat162float(h1);
    float l2 = v.z - __bfloat162float(h2), l3 = v.w - __bfloat162float(h3);
    uint2 hv, lv;
    hv.x = (uint32_t)__bfloat16_as_ushort(h0) | ((uint32_t)__bfloat16_as_ushort(h1) << 16);
    hv.y = (uint32_t)__bfloat16_as_ushort(h2) | ((uint32_t)__bfloat16_as_ushort(h3) << 16);
    lv.x = (uint32_t)__bfloat16_as_ushort(__float2bfloat16(l0)) |
           ((uint32_t)__bfloat16_as_ushort(__float2bfloat16(l1)) << 16);
    lv.y = (uint32_t)__bfloat16_as_ushort(__float2bfloat16(l2)) |
           ((uint32_t)__bfloat16_as_ushort(__float2bfloat16(l3)) << 16);
    ((uint2*)a.h[seg])[i] = hv;
    ((uint2*)a.l[seg])[i] = lv;
}

// ---------------------------------------------------------------------------
// mma.sync split-bf16 GEMM (pre-split bf16 operands, cp.async 2-stage).
// Tile M=128, N=64, K-tile=64; 256 threads (8 warps, 4x2 grid, 32x32/warp).
// C = A @ B^T, K-major SW128 smem tiles.  3 HMMA passes per fragment.
// EPI:  0 LIN (bias + split store, ld 1024)            [Q/K projections]
//       1 VT  (bias + split store transposed per-head) [V projection]
//       4 OUT (bias, fp32 store ld 1024)               [output projection]
// ---------------------------------------------------------------------------
#define MT 128
#define NT 64
#define KT 64
#define STG_STRIDE 49152
#define OFF_AH 0
#define OFF_AL 16384
#define OFF_BH 32768
#define OFF_BL 40960
#define SM_PIPE  98304

template <int EPI>
__global__ void __launch_bounds__(256)
mma_gemm(const __nv_bfloat16* __restrict__ Ah, const __nv_bfloat16* __restrict__ Al,
         const __nv_bfloat16* __restrict__ Bh, const __nv_bfloat16* __restrict__ Bl,
         const float* __restrict__ bias, float* __restrict__ outF,
         __nv_bfloat16* __restrict__ outH, __nv_bfloat16* __restrict__ outL,
         int K, int lda, int ldb)
{
    extern __shared__ uint8_t dsm[];
    const uint32_t sb = smem_u32(dsm);
    const int tid = threadIdx.x, wid = tid >> 5, lane = tid & 31;
    const int wm = wid >> 1, wn = wid & 1;
    const int n0 = blockIdx.x * NT, m0 = blockIdx.y * MT;

    float acc[2][4][4];
#pragma unroll
    for (int i = 0; i < 2; i++)
#pragma unroll
        for (int j = 0; j < 4; j++)
#pragma unroll
            for (int r = 0; r < 4; r++) acc[i][j][r] = 0.0f;

    const int lrow = lane & 15, lkh = lane >> 4;

    const int ntiles = K / KT;
    auto stage = [&](int kti, int buf) {
        const uint32_t b0 = sb + buf * STG_STRIDE;
        const int kt = kti * KT;
#pragma unroll
        for (int i = 0; i < 4; i++) {
            int chunk = tid + i * 256;
            int row = chunk >> 3, c16 = chunk & 7;
            long g = (long)(m0 + row) * lda + kt + c16 * 8;
            uint32_t so = SWZ((uint32_t)(row * 128 + c16 * 16));
            cp16(b0 + OFF_AH + so, Ah + g);
            cp16(b0 + OFF_AL + so, Al + g);
        }
#pragma unroll
        for (int i = 0; i < 2; i++) {
            int chunk = tid + i * 256;
            int row = chunk >> 3, c16 = chunk & 7;
            long g = (long)(n0 + row) * ldb + kt + c16 * 8;
            uint32_t so = SWZ((uint32_t)(row * 128 + c16 * 16));
            cp16(b0 + OFF_BH + so, Bh + g);
            cp16(b0 + OFF_BL + so, Bl + g);
        }
    };
    stage(0, 0);
    CP_COMMIT();
    for (int t = 0; t < ntiles; t++) {
        if (t + 1 < ntiles) { stage(t + 1, (t + 1) & 1); CP_COMMIT(); CP_WAIT1(); }
        else { CP_WAIT0(); }
        __syncthreads();
        const uint32_t b0 = sb + (t & 1) * STG_STRIDE;
#pragma unroll
        for (int ks = 0; ks < 4; ks++) {
            const uint32_t kb = ks * 32 + lkh * 16;
            uint32_t ah[2][4], al[2][4];
#pragma unroll
            for (int ms = 0; ms < 2; ms++) {
                uint32_t ro = (uint32_t)(wm * 32 + ms * 16 + lrow) * 128 + kb;
                ldsm_x4(ah[ms][0], ah[ms][1], ah[ms][2], ah[ms][3], b0 + OFF_AH + SWZ(ro));
                ldsm_x4(al[ms][0], al[ms][1], al[ms][2], al[ms][3], b0 + OFF_AL + SWZ(ro));
            }
            uint32_t bh[4][2], bl[4][2];
#pragma unroll
            for (int half = 0; half < 2; half++) {
                uint32_t ro = (uint32_t)(wn * 32 + half * 16 + lrow) * 128 + kb;
                uint32_t r0, r1, r2, r3;
                ldsm_x4(r0, r1, r2, r3, b0 + OFF_BH + SWZ(ro));
                bh[half * 2 + 0][0] = r0; bh[half * 2 + 0][1] = r2;
                bh[half * 2 + 1][0] = r1; bh[half * 2 + 1][1] = r3;
                ldsm_x4(r0, r1, r2, r3, b0 + OFF_BL + SWZ(ro));
                bl[half * 2 + 0][0] = r0; bl[half * 2 + 0][1] = r2;
                bl[half * 2 + 1][0] = r1; bl[half * 2 + 1][1] = r3;
            }
#pragma unroll
            for (int ms = 0; ms < 2; ms++)
#pragma unroll
                for (int nb = 0; nb < 4; nb++) {
                    mma16816(acc[ms][nb], ah[ms], bh[nb][0], bh[nb][1]);
                    mma16816(acc[ms][nb], al[ms], bh[nb][0], bh[nb][1]);
                    mma16816(acc[ms][nb], ah[ms], bl[nb][0], bl[nb][1]);
                }
        }
        __syncthreads();
    }

    // ---- epilogue: regs -> padded smem staging -> coalesced global ----
    float* st = (float*)dsm;                     // [128][65] fp32
    {
        const int lr = lane >> 2, lc = (lane & 3) * 2;
#pragma unroll
        for (int ms = 0; ms < 2; ms++)
#pragma unroll
            for (int nb = 0; nb < 4; nb++) {
                int r = wm * 32 + ms * 16 + lr;
                int c = wn * 32 + nb * 8 + lc;
                st[r * 65 + c]            = acc[ms][nb][0];
                st[r * 65 + c + 1]        = acc[ms][nb][1];
                st[(r + 8) * 65 + c]      = acc[ms][nb][2];
                st[(r + 8) * 65 + c + 1]  = acc[ms][nb][3];
            }
    }
    __syncthreads();

    if (EPI == 4) {            // OUT: fp32 + bias, ld 1024
        for (int i = tid; i < MT * NT; i += 256) {
            int row = i >> 6, c = i & 63;
            outF[(long)(m0 + row) * 1024 + n0 + c] = st[row * 65 + c] + bias[n0 + c];
        }
    } else if (EPI == 0) {     // LIN: bias + split, ld 1024
        for (int i = tid; i < MT * NT; i += 256) {
            int row = i >> 6, c = i & 63;
            float v = st[row * 65 + c] + bias[n0 + c];
            long o = (long)(m0 + row) * 1024 + n0 + c;
            __nv_bfloat16 h = __float2bfloat16(v);
            outH[o] = h;
            outL[o] = __float2bfloat16(v - __bfloat162float(h));
        }
    } else {                   // VT: bias + split, transposed per-head [BH,64,S]
        for (int i = tid; i < MT * NT; i += 256) {
            int j = i >> 7, rl = i & 127;
            int r = m0 + rl, cg = n0 + j;
            float v = st[rl * 65 + j] + bias[cg];
            int b = r >> 11, s = r & 2047, hh = cg >> 6, jj = cg & 63;
            long o = ((long)(b * 16 + hh) * 64 + jj) * 2048 + s;
            __nv_bfloat16 h = __float2bfloat16(v);
            outH[o] = h;
            outL[o] = __float2bfloat16(v - __bfloat162float(h));
        }
    }
}

// ---------------------------------------------------------------------------
// Fused scores + softmax + context, single-S-computation version.
// Pass A: S tiles once; e = exp(s/8); row-sums; store UNNORMALIZED e to attn
//         (fragment-layout stores; each thread owns its addresses).
// Pass B: reload own e fragments (same-thread RAW via global), scale by 1/L,
//         rewrite normalized attn, split P to bf16 hi/lo, O += P @ V^T.
// smem: Q 32K + 2-stage KV buffer 32K (K in pass A, V in pass B) + red ~1.5K.
// ---------------------------------------------------------------------------
#define FB_QH   0
#define FB_QL   16384
#define FB_KV0  32768            // stage s at FB_KV0 + s*16384: hi +0, lo +8192
#define FB_KVS  16384
#define FB_PART 65536            // float[2][128]
#define FB_ROWL 66560            // float[128]
#define FB_SM   67072

__global__ void __launch_bounds__(256)
fused_attn_k(const __nv_bfloat16* __restrict__ qh, const __nv_bfloat16* __restrict__ ql,
             const __nv_bfloat16* __restrict__ kh, const __nv_bfloat16* __restrict__ kl,
             const __nv_bfloat16* __restrict__ vth, const __nv_bfloat16* __restrict__ vtl,
             float* __restrict__ attn,
             __nv_bfloat16* __restrict__ ch, __nv_bfloat16* __restrict__ cl)
{
    extern __shared__ uint8_t dsm[];
    const uint32_t sb = smem_u32(dsm);
    const int tid = threadIdx.x, wid = tid >> 5, lane = tid & 31;
    const int wm = wid >> 1, wn = wid & 1;
    const int lrow = lane & 15, lkh = lane >> 4;
    const int lr = lane >> 2, lc = lane & 3;
    const int m0 = blockIdx.x * 128;
    const int z = blockIdx.y;
    const long base = (long)(z >> 4) * 2048L * 1024 + (long)(z & 15) * 64;
    const __nv_bfloat16* qh_h = qh + base;
    const __nv_bfloat16* ql_h = ql + base;
    const __nv_bfloat16* kh_h = kh + base;
    const __nv_bfloat16* kl_h = kl + base;
    const __nv_bfloat16* vh_h = vth + (long)z * 64L * 2048;
    const __nv_bfloat16* vl_h = vtl + (long)z * 64L * 2048;

    float* part  = (float*)(dsm + FB_PART);
    float* row_l = (float*)(dsm + FB_ROWL);

    // per-thread fragment base rows in attn
    const long frag_rb0 = ((long)z * 2048 + m0 + wm * 32 + lr) * 2048;

    auto stage_k = [&](int t, int buf) {
        const uint32_t sd = sb + FB_KV0 + buf * FB_KVS;
#pragma unroll
        for (int i = 0; i < 2; i++) {
            int chunk = tid + i * 256;               // 512: 64 rows x 8 chunks
            int row = chunk >> 3, c16 = chunk & 7;
            long g = (long)(t * 64 + row) * 1024 + c16 * 8;
            uint32_t so = SWZ((uint32_t)(row * 128 + c16 * 16));
            cp16(sd + so, kh_h + g);
            cp16(sd + 8192 + so, kl_h + g);
        }
    };
    auto stage_v = [&](int t, int buf) {
        const uint32_t sd = sb + FB_KV0 + buf * FB_KVS;
#pragma unroll
        for (int i = 0; i < 2; i++) {
            int chunk = tid + i * 256;               // row = dk 0..63
            int row = chunk >> 3, c16 = chunk & 7;
            long g = (long)row * 2048 + t * 64 + c16 * 8;
            uint32_t so = SWZ((uint32_t)(row * 128 + c16 * 16));
            cp16(sd + so, vh_h + g);
            cp16(sd + 8192 + so, vl_h + g);
        }
    };
    auto compute_tile = [&](int buf, float acc[2][4][4]) {
#pragma unroll
        for (int i = 0; i < 2; i++)
#pragma unroll
            for (int j = 0; j < 4; j++)
#pragma unroll
                for (int r = 0; r < 4; r++) acc[i][j][r] = 0.0f;
        const uint32_t kbh = sb + FB_KV0 + buf * FB_KVS;
        const uint32_t kbl = kbh + 8192;
#pragma unroll
        for (int ks = 0; ks < 4; ks++) {
            const uint32_t kb = ks * 32 + lkh * 16;
            uint32_t ah[2][4], al[2][4];
#pragma unroll
            for (int ms = 0; ms < 2; ms++) {
                uint32_t ro = (uint32_t)(wm * 32 + ms * 16 + lrow) * 128 + kb;
                ldsm_x4(ah[ms][0], ah[ms][1], ah[ms][2], ah[ms][3], sb + FB_QH + SWZ(ro));
                ldsm_x4(al[ms][0], al[ms][1], al[ms][2], al[ms][3], sb + FB_QL + SWZ(ro));
            }
            uint32_t bh[4][2], bl[4][2];
#pragma unroll
            for (int half = 0; half < 2; half++) {
                uint32_t ro = (uint32_t)(wn * 32 + half * 16 + lrow) * 128 + kb;
                uint32_t r0, r1, r2, r3;
                ldsm_x4(r0, r1, r2, r3, kbh + SWZ(ro));
                bh[half * 2 + 0][0] = r0; bh[half * 2 + 0][1] = r2;
                bh[half * 2 + 1][0] = r1; bh[half * 2 + 1][1] = r3;
                ldsm_x4(r0, r1, r2, r3, kbl + SWZ(ro));
                bl[half * 2 + 0][0] = r0; bl[half * 2 + 0][1] = r2;
                bl[half * 2 + 1][0] = r1; bl[half * 2 + 1][1] = r3;
            }
#pragma unroll
            for (int ms = 0; ms < 2; ms++)
#pragma unroll
                for (int nb = 0; nb < 4; nb++) {
                    mma16816(acc[ms][nb], ah[ms], bh[nb][0], bh[nb][1]);
                    mma16816(acc[ms][nb], al[ms], bh[nb][0], bh[nb][1]);
                    mma16816(acc[ms][nb], ah[ms], bl[nb][0], bl[nb][1]);
                }
        }
    };

    // ---- prologue: q tile + k tile 0 ----
#pragma unroll
    for (int i = 0; i < 4; i++) {
        int chunk = tid + i * 256;                   // 1024: 128 rows x 8
        int row = chunk >> 3, c16 = chunk & 7;
        long g = (long)(m0 + row) * 1024 + c16 * 8;
        uint32_t so = SWZ((uint32_t)(row * 128 + c16 * 16));
        cp16(sb + FB_QH + so, qh_h + g);
        cp16(sb + FB_QL + so, ql_h + g);
    }
    if (tid < 128) row_l[tid] = 0.0f;
    stage_k(0, 0);
    CP_COMMIT();

    float acc[2][4][4];

    // ---- pass A: S once; e = exp; row sums; store unnormalized e ----
    for (int t = 0; t < 32; t++) {
        if (t + 1 < 32) { stage_k(t + 1, (t + 1) & 1); CP_COMMIT(); CP_WAIT1(); }
        else { CP_WAIT0(); }
        __syncthreads();
        compute_tile(t & 1, acc);

        // exp in place + row-sum partials
#pragma unroll
        for (int ms = 0; ms < 2; ms++) {
            float s0 = 0.0f, s1 = 0.0f;
#pragma unroll
            for (int nb = 0; nb < 4; nb++) {
                acc[ms][nb][0] = __expf(acc[ms][nb][0] * 0.125f);
                acc[ms][nb][1] = __expf(acc[ms][nb][1] * 0.125f);
                acc[ms][nb][2] = __expf(acc[ms][nb][2] * 0.125f);
                acc[ms][nb][3] = __expf(acc[ms][nb][3] * 0.125f);
                s0 += acc[ms][nb][0] + acc[ms][nb][1];
                s1 += acc[ms][nb][2] + acc[ms][nb][3];
            }
            s0 += __shfl_xor_sync(0xffffffffu, s0, 1);
            s0 += __shfl_xor_sync(0xffffffffu, s0, 2);
            s1 += __shfl_xor_sync(0xffffffffu, s1, 1);
            s1 += __shfl_xor_sync(0xffffffffu, s1, 2);
            if (lc == 0) {
                part[wn * 128 + wm * 32 + ms * 16 + lr]     = s0;
                part[wn * 128 + wm * 32 + ms * 16 + 8 + lr] = s1;
            }
        }

        // store unnormalized e fragments
        const int colb = t * 64 + wn * 32 + lc * 2;
#pragma unroll
        for (int ms = 0; ms < 2; ms++) {
            long rb0 = frag_rb0 + (long)(ms * 16) * 2048;
            long rb1 = rb0 + 8L * 2048;
#pragma unroll
            for (int nb = 0; nb < 4; nb++) {
                *(float2*)(attn + rb0 + colb + nb * 8) =
                    make_float2(acc[ms][nb][0], acc[ms][nb][1]);
                *(float2*)(attn + rb1 + colb + nb * 8) =
                    make_float2(acc[ms][nb][2], acc[ms][nb][3]);
            }
        }
        __syncthreads();
        if (tid < 128) row_l[tid] += part[tid] + part[128 + tid];
    }
    __syncthreads();
    float inv[2][2];
#pragma unroll
    for (int ms = 0; ms < 2; ms++) {
        inv[ms][0] = 1.0f / row_l[wm * 32 + ms * 16 + lr];
        inv[ms][1] = 1.0f / row_l[wm * 32 + ms * 16 + 8 + lr];
    }

    // O accumulator: 32 rows x 64 dk per warp (partial over this warp's keys)
    float accO[2][8][4];
#pragma unroll
    for (int ms = 0; ms < 2; ms++)
#pragma unroll
        for (int dn = 0; dn < 8; dn++)
#pragma unroll
            for (int r = 0; r < 4; r++) accO[ms][dn][r] = 0.0f;

    // ---- pass B: reload e, normalize+rewrite attn, O += P @ V^T ----
    stage_v(0, 0);
    CP_COMMIT();
    for (int t = 0; t < 32; t++) {
        if (t + 1 < 32) { stage_v(t + 1, (t + 1) & 1); CP_COMMIT(); CP_WAIT1(); }
        else { CP_WAIT0(); }

        // reload own e fragments, normalize, rewrite attn
        const int colb = t * 64 + wn * 32 + lc * 2;
#pragma unroll
        for (int ms = 0; ms < 2; ms++) {
            long rb0 = frag_rb0 + (long)(ms * 16) * 2048;
            long rb1 = rb0 + 8L * 2048;
#pragma unroll
            for (int nb = 0; nb < 4; nb++) {
                float2 e0 = *(const float2*)(attn + rb0 + colb + nb * 8);
                float2 e1 = *(const float2*)(attn + rb1 + colb + nb * 8);
                acc[ms][nb][0] = e0.x * inv[ms][0];
                acc[ms][nb][1] = e0.y * inv[ms][0];
                acc[ms][nb][2] = e1.x * inv[ms][1];
                acc[ms][nb][3] = e1.y * inv[ms][1];
                *(float2*)(attn + rb0 + colb + nb * 8) =
                    make_float2(acc[ms][nb][0], acc[ms][nb][1]);
                *(float2*)(attn + rb1 + colb + nb * 8) =
                    make_float2(acc[ms][nb][2], acc[ms][nb][3]);
            }
        }

        __syncthreads();                              // V tile ready (cp.async)
        const uint32_t vbh = sb + FB_KV0 + (t & 1) * FB_KVS;
        const uint32_t vbl = vbh + 8192;
#pragma unroll
        for (int kh2 = 0; kh2 < 2; kh2++) {
            uint32_t vh[8][2], vl[8][2];
#pragma unroll
            for (int dh = 0; dh < 4; dh++) {
                uint32_t ro = (uint32_t)(dh * 16 + lrow) * 128 +
                              (uint32_t)(wn * 32 + kh2 * 16) * 2 + lkh * 16;
                uint32_t r0, r1, r2, r3;
                ldsm_x4(r0, r1, r2, r3, vbh + SWZ(ro));
                vh[dh * 2 + 0][0] = r0; vh[dh * 2 + 0][1] = r2;
                vh[dh * 2 + 1][0] = r1; vh[dh * 2 + 1][1] = r3;
                ldsm_x4(r0, r1, r2, r3, vbl + SWZ(ro));
                vl[dh * 2 + 0][0] = r0; vl[dh * 2 + 0][1] = r2;
                vl[dh * 2 + 1][0] = r1; vl[dh * 2 + 1][1] = r3;
            }
#pragma unroll
            for (int ms = 0; ms < 2; ms++) {
                const float* c0 = acc[ms][2 * kh2];
                const float* c1 = acc[ms][2 * kh2 + 1];
                uint32_t ph[4], pl[4];
                ph[0] = pack_bf16(c0[0], c0[1]);
                ph[1] = pack_bf16(c0[2], c0[3]);
                ph[2] = pack_bf16(c1[0], c1[1]);
                ph[3] = pack_bf16(c1[2], c1[3]);
                pl[0] = pack_bf16(c0[0] - bf16lo_f(ph[0]), c0[1] - bf16hi_f(ph[0]));
                pl[1] = pack_bf16(c0[2] - bf16lo_f(ph[1]), c0[3] - bf16hi_f(ph[1]));
                pl[2] = pack_bf16(c1[0] - bf16lo_f(ph[2]), c1[1] - bf16hi_f(ph[2]));
                pl[3] = pack_bf16(c1[2] - bf16lo_f(ph[3]), c1[3] - bf16hi_f(ph[3]));
#pragma unroll
                for (int dn = 0; dn < 8; dn++) {
                    mma16816(accO[ms][dn], ph, vh[dn][0], vh[dn][1]);
                    mma16816(accO[ms][dn], pl, vh[dn][0], vh[dn][1]);
                    mma16816(accO[ms][dn], ph, vl[dn][0], vl[dn][1]);
                }
            }
        }
        __syncthreads();                              // V buffer reuse guard
    }

    // ---- ctx epilogue: cross-wn reduce in smem, split store [B,S,D] ----
    float* st = (float*)dsm;                     // [128][65] fp32
    {
        const int lc2 = lc * 2;
        if (wn == 0) {
#pragma unroll
            for (int ms = 0; ms < 2; ms++)
#pragma unroll
                for (int dn = 0; dn < 8; dn++) {
                    int r = wm * 32 + ms * 16 + lr;
                    int c = dn * 8 + lc2;
                    st[r * 65 + c]           = accO[ms][dn][0];
                    st[r * 65 + c + 1]       = accO[ms][dn][1];
                    st[(r + 8) * 65 + c]     = accO[ms][dn][2];
                    st[(r + 8) * 65 + c + 1] = accO[ms][dn][3];
                }
        }
        __syncthreads();
        if (wn == 1) {
#pragma unroll
            for (int ms = 0; ms < 2; ms++)
#pragma unroll
                for (int dn = 0; dn < 8; dn++) {
                    int r = wm * 32 + ms * 16 + lr;
                    int c = dn * 8 + lc2;
                    st[r * 65 + c]           += accO[ms][dn][0];
                    st[r * 65 + c + 1]       += accO[ms][dn][1];
                    st[(r + 8) * 65 + c]     += accO[ms][dn][2];
                    st[(r + 8) * 65 + c + 1] += accO[ms][dn][3];
                }
        }
        __syncthreads();
    }
    {
        const int b = z >> 4, hh = z & 15;
        for (int i = tid; i < 128 * 64; i += 256) {
            int row = i >> 6, c = i & 63;
            float v = st[row * 65 + c];
            long o = (long)((b << 11) + m0 + row) * 1024 + hh * 64 + c;
            __nv_bfloat16 h = __float2bfloat16(v);
            ch[o] = h;
            cl[o] = __float2bfloat16(v - __bfloat162float(h));
        }
    }
}

// ---------------------------------------------------------------------------
extern "C" void kernel_launch(void* const* d_in, const int* in_sizes, int n_in,
                              void* d_out, int out_size)
{
    const float* Q  = (const float*)d_in[0];
    const float* K  = (const float*)d_in[1];
    const float* V  = (const float*)d_in[2];
    const float* Wq = (const float*)d_in[3];
    const float* bq = (const float*)d_in[4];
    const float* Wk = (const float*)d_in[5];
    const float* bk = (const float*)d_in[6];
    const float* Wv = (const float*)d_in[7];
    const float* bv = (const float*)d_in[8];
    const float* Wo = (const float*)d_in[9];
    const float* bo = (const float*)d_in[10];
    float* out = (float*)d_out;

    __nv_bfloat16 *Qh, *Ql, *Kh, *Kl, *Vh, *Vl;
    __nv_bfloat16 *Wqh, *Wql, *Wkh, *Wkl, *Wvh, *Wvl, *Woh, *Wol;
    __nv_bfloat16 *qh, *ql, *kh, *kl, *vth, *vtl, *ch, *cl;
    float* attn_scratch;
    cudaGetSymbolAddress((void**)&Qh, g_Qh);   cudaGetSymbolAddress((void**)&Ql, g_Ql);
    cudaGetSymbolAddress((void**)&Kh, g_Kh);   cudaGetSymbolAddress((void**)&Kl, g_Kl);
    cudaGetSymbolAddress((void**)&Vh, g_Vh);   cudaGetSymbolAddress((void**)&Vl, g_Vl);
    cudaGetSymbolAddress((void**)&Wqh, g_Wqh); cudaGetSymbolAddress((void**)&Wql, g_Wql);
    cudaGetSymbolAddress((void**)&Wkh, g_Wkh); cudaGetSymbolAddress((void**)&Wkl, g_Wkl);
    cudaGetSymbolAddress((void**)&Wvh, g_Wvh); cudaGetSymbolAddress((void**)&Wvl, g_Wvl);
    cudaGetSymbolAddress((void**)&Woh, g_Woh); cudaGetSymbolAddress((void**)&Wol, g_Wol);
    cudaGetSymbolAddress((void**)&qh, g_qh);   cudaGetSymbolAddress((void**)&ql, g_ql);
    cudaGetSymbolAddress((void**)&kh, g_kh);   cudaGetSymbolAddress((void**)&kl, g_kl);
    cudaGetSymbolAddress((void**)&vth, g_vth); cudaGetSymbolAddress((void**)&vtl, g_vtl);
    cudaGetSymbolAddress((void**)&ch, g_ch);   cudaGetSymbolAddress((void**)&cl, g_cl);
    cudaGetSymbolAddress((void**)&attn_scratch, g_attn);

    float* attn = ((long)out_size >= OUT_TOTAL) ? (out + OUT0) : attn_scratch;

    cudaFuncSetAttribute(mma_gemm<0>, cudaFuncAttributeMaxDynamicSharedMemorySize, SM_PIPE);
    cudaFuncSetAttribute(mma_gemm<1>, cudaFuncAttributeMaxDynamicSharedMemorySize, SM_PIPE);
    cudaFuncSetAttribute(mma_gemm<4>, cudaFuncAttributeMaxDynamicSharedMemorySize, SM_PIPE);
    cudaFuncSetAttribute(fused_attn_k, cudaFuncAttributeMaxDynamicSharedMemorySize, FB_SM);

    // 0) One-launch split of all 7 fp32 inputs into bf16 hi/lo
    {
        SplitArgs a;
        a.x[0] = Q;  a.h[0] = Qh;  a.l[0] = Ql;  a.n4[0] = TOKENS * DMODEL / 4;
        a.x[1] = K;  a.h[1] = Kh;  a.l[1] = Kl;  a.n4[1] = TOKENS * DMODEL / 4;
        a.x[2] = V;  a.h[2] = Vh;  a.l[2] = Vl;  a.n4[2] = TOKENS * DMODEL / 4;
        a.x[3] = Wq; a.h[3] = Wqh; a.l[3] = Wql; a.n4[3] = DMODEL * DMODEL / 4;
        a.x[4] = Wk; a.h[4] = Wkh; a.l[4] = Wkl; a.n4[4] = DMODEL * DMODEL / 4;
        a.x[5] = Wv; a.h[5] = Wvh; a.l[5] = Wvl; a.n4[5] = DMODEL * DMODEL / 4;
        a.x[6] = Wo; a.h[6] = Woh; a.l[6] = Wol; a.n4[6] = DMODEL * DMODEL / 4;
        dim3 gs((TOKENS * DMODEL / 4 + 255) / 256, 7, 1);
        split_all<<<gs, 256>>>(a);
    }

    // 1-3) Projections: [4096,1024] @ W^T + b (pipelined)
    dim3 gp(DMODEL / NT, TOKENS / MT, 1);                       // (16, 32)
    mma_gemm<0><<<gp, 256, SM_PIPE>>>(Qh, Ql, Wqh, Wql, bq, nullptr, qh, ql,
                                      DMODEL, DMODEL, DMODEL);
    mma_gemm<0><<<gp, 256, SM_PIPE>>>(Kh, Kl, Wkh, Wkl, bk, nullptr, kh, kl,
                                      DMODEL, DMODEL, DMODEL);
    mma_gemm<1><<<gp, 256, SM_PIPE>>>(Vh, Vl, Wvh, Wvl, bv, nullptr, vth, vtl,
                                      DMODEL, DMODEL, DMODEL);

    // 4) Fused scores + softmax + context (S computed once)
    dim3 gf(SEQ / 128, BH, 1);                                  // (16, 32)
    fused_attn_k<<<gf, 256, FB_SM>>>(qh, ql, kh, kl, vth, vtl, attn, ch, cl);

    // 5) Output projection: ctx @ Wo^T + bo -> out fp32 (pipelined)
    mma_gemm<4><<<gp, 256, SM_PIPE>>>(ch, cl, Woh, Wol, bo, out, nullptr, nullptr,
                                      DMODEL, DMODEL, DMODEL);

    (void)n_in; (void)in_sizes;
}

// round 9
// speedup vs baseline: 1.3267x; 1.3267x over previous
#include <cuda_runtime.h>
#include <cuda_bf16.h>
#include <cstdint>

// ---------------------------------------------------------------------------
// Problem constants
// ---------------------------------------------------------------------------
#define BATCH   2
#define SEQ     2048
#define DMODEL  1024
#define NHEAD   16
#define DK      64
#define BH      (BATCH * NHEAD)              // 32
#define TOKENS  (BATCH * SEQ)                // 4096
#define OUT0    (TOKENS * DMODEL)            // 4,194,304
#define ATTN_N  ((long)BH * SEQ * SEQ)       // 134,217,728
#define OUT_TOTAL (OUT0 + ATTN_N)

// ---------------------------------------------------------------------------
// Scratch (static device arrays; no cudaMalloc anywhere)
// ---------------------------------------------------------------------------
__device__ __nv_bfloat16 g_Qh[TOKENS * DMODEL], g_Ql[TOKENS * DMODEL];
__device__ __nv_bfloat16 g_Kh[TOKENS * DMODEL], g_Kl[TOKENS * DMODEL];
__device__ __nv_bfloat16 g_Vh[TOKENS * DMODEL], g_Vl[TOKENS * DMODEL];
__device__ __nv_bfloat16 g_Wqh[DMODEL * DMODEL], g_Wql[DMODEL * DMODEL];
__device__ __nv_bfloat16 g_Wkh[DMODEL * DMODEL], g_Wkl[DMODEL * DMODEL];
__device__ __nv_bfloat16 g_Wvh[DMODEL * DMODEL], g_Wvl[DMODEL * DMODEL];
__device__ __nv_bfloat16 g_Woh[DMODEL * DMODEL], g_Wol[DMODEL * DMODEL];
__device__ __nv_bfloat16 g_qh[TOKENS * DMODEL], g_ql[TOKENS * DMODEL];   // [B,S,H*64]
__device__ __nv_bfloat16 g_kh[TOKENS * DMODEL], g_kl[TOKENS * DMODEL];   // [B,S,H*64]
__device__ __nv_bfloat16 g_vth[BH * DK * SEQ], g_vtl[BH * DK * SEQ];     // [BH,64,S]
__device__ __nv_bfloat16 g_ch[TOKENS * DMODEL], g_cl[TOKENS * DMODEL];   // ctx [B,S,D]
__device__ float g_attn[ATTN_N];                 // fallback if d_out lacks attn

// ---------------------------------------------------------------------------
// Helpers
// ---------------------------------------------------------------------------
__device__ __forceinline__ uint32_t smem_u32(const void* p) {
    uint32_t a;
    asm("{ .reg .u64 t; cvta.to.shared.u64 t, %1; cvt.u32.u64 %0, t; }"
        : "=r"(a) : "l"(p));
    return a;
}
#define SWZ(off) ((off) ^ (((off) >> 3) & 0x70))

__device__ __forceinline__ void ldsm_x4(uint32_t& r0, uint32_t& r1,
                                        uint32_t& r2, uint32_t& r3, uint32_t a) {
    asm volatile("ldmatrix.sync.aligned.m8n8.x4.shared.b16 {%0,%1,%2,%3}, [%4];"
                 : "=r"(r0), "=r"(r1), "=r"(r2), "=r"(r3) : "r"(a));
}
__device__ __forceinline__ void mma16816(float* c, const uint32_t* a,
                                         uint32_t b0, uint32_t b1) {
    asm volatile(
        "mma.sync.aligned.m16n8k16.row.col.f32.bf16.bf16.f32 "
        "{%0,%1,%2,%3}, {%4,%5,%6,%7}, {%8,%9}, {%0,%1,%2,%3};"
        : "+f"(c[0]), "+f"(c[1]), "+f"(c[2]), "+f"(c[3])
        : "r"(a[0]), "r"(a[1]), "r"(a[2]), "r"(a[3]), "r"(b0), "r"(b1));
}
__device__ __forceinline__ void cp16(uint32_t dst, const void* src) {
    asm volatile("cp.async.cg.shared.global [%0], [%1], 16;"
                 :: "r"(dst), "l"(src) : "memory");
}
#define CP_COMMIT() asm volatile("cp.async.commit_group;" ::: "memory")
#define CP_WAIT1()  asm volatile("cp.async.wait_group 1;" ::: "memory")
#define CP_WAIT0()  asm volatile("cp.async.wait_group 0;" ::: "memory")

// pack two fp32 -> bf16x2 register (first arg in low half)
__device__ __forceinline__ uint32_t pack_bf16(float lo, float hi) {
    uint32_t r;
    asm("cvt.rn.bf16x2.f32 %0, %1, %2;" : "=r"(r) : "f"(hi), "f"(lo));
    return r;
}
__device__ __forceinline__ float bf16lo_f(uint32_t r) {
    return __bfloat162float(__ushort_as_bfloat16((unsigned short)(r & 0xffffu)));
}
__device__ __forceinline__ float bf16hi_f(uint32_t r) {
    return __bfloat162float(__ushort_as_bfloat16((unsigned short)(r >> 16)));
}

// ---------------------------------------------------------------------------
// One-launch fp32 -> bf16 hi/lo split over all 7 inputs (grid.y = segment)
// ---------------------------------------------------------------------------
struct SplitArgs {
    const float* x[7];
    __nv_bfloat16* h[7];
    __nv_bfloat16* l[7];
    int n4[7];                 // float4 group count per segment
};

__global__ void __launch_bounds__(256)
split_all(SplitArgs a)
{
    const int seg = blockIdx.y;
    const int i = blockIdx.x * 256 + threadIdx.x;
    if (i >= a.n4[seg]) return;
    float4 v = ((const float4*)a.x[seg])[i];
    __nv_bfloat16 h0 = __float2bfloat16(v.x), h1 = __float2bfloat16(v.y);
    __nv_bfloat16 h2 = __float2bfloat16(v.z), h3 = __float2bfloat16(v.w);
    float l0 = v.x - __bfloat162float(h0), l1 = v.y - __bfloat162float(h1);
    float l2 = v.z - __bfloat162float(h2), l3 = v.w - __bfloat162float(h3);
    uint2 hv, lv;
    hv.x = (uint32_t)__bfloat16_as_ushort(h0) | ((uint32_t)__bfloat16_as_ushort(h1) << 16);
    hv.y = (uint32_t)__bfloat16_as_ushort(h2) | ((uint32_t)__bfloat16_as_ushort(h3) << 16);
    lv.x = (uint32_t)__bfloat16_as_ushort(__float2bfloat16(l0)) |
           ((uint32_t)__bfloat16_as_ushort(__float2bfloat16(l1)) << 16);
    lv.y = (uint32_t)__bfloat16_as_ushort(__float2bfloat16(l2)) |
           ((uint32_t)__bfloat16_as_ushort(__float2bfloat16(l3)) << 16);
    ((uint2*)a.h[seg])[i] = hv;
    ((uint2*)a.l[seg])[i] = lv;
}

// ---------------------------------------------------------------------------
// mma.sync split-bf16 GEMM (pre-split bf16 operands, cp.async 2-stage).
// Tile M=128, N=64, K-tile=64; 256 threads (8 warps, 4x2 grid, 32x32/warp).
// C = A @ B^T, K-major SW128 smem tiles.  3 HMMA passes per fragment.
// EPI:  0 LIN (bias + split store, ld 1024)            [Q/K projections]
//       1 VT  (bias + split store transposed per-head) [V projection]
//       4 OUT (bias, fp32 store ld 1024)               [output projection]
// ---------------------------------------------------------------------------
#define MT 128
#define NT 64
#define KT 64
#define STG_STRIDE 49152
#define OFF_AH 0
#define OFF_AL 16384
#define OFF_BH 32768
#define OFF_BL 40960
#define SM_PIPE  98304

template <int EPI>
__global__ void __launch_bounds__(256)
mma_gemm(const __nv_bfloat16* __restrict__ Ah, const __nv_bfloat16* __restrict__ Al,
         const __nv_bfloat16* __restrict__ Bh, const __nv_bfloat16* __restrict__ Bl,
         const float* __restrict__ bias, float* __restrict__ outF,
         __nv_bfloat16* __restrict__ outH, __nv_bfloat16* __restrict__ outL,
         int K, int lda, int ldb)
{
    extern __shared__ uint8_t dsm[];
    const uint32_t sb = smem_u32(dsm);
    const int tid = threadIdx.x, wid = tid >> 5, lane = tid & 31;
    const int wm = wid >> 1, wn = wid & 1;
    const int n0 = blockIdx.x * NT, m0 = blockIdx.y * MT;

    float acc[2][4][4];
#pragma unroll
    for (int i = 0; i < 2; i++)
#pragma unroll
        for (int j = 0; j < 4; j++)
#pragma unroll
            for (int r = 0; r < 4; r++) acc[i][j][r] = 0.0f;

    const int lrow = lane & 15, lkh = lane >> 4;

    const int ntiles = K / KT;
    auto stage = [&](int kti, int buf) {
        const uint32_t b0 = sb + buf * STG_STRIDE;
        const int kt = kti * KT;
#pragma unroll
        for (int i = 0; i < 4; i++) {
            int chunk = tid + i * 256;
            int row = chunk >> 3, c16 = chunk & 7;
            long g = (long)(m0 + row) * lda + kt + c16 * 8;
            uint32_t so = SWZ((uint32_t)(row * 128 + c16 * 16));
            cp16(b0 + OFF_AH + so, Ah + g);
            cp16(b0 + OFF_AL + so, Al + g);
        }
#pragma unroll
        for (int i = 0; i < 2; i++) {
            int chunk = tid + i * 256;
            int row = chunk >> 3, c16 = chunk & 7;
            long g = (long)(n0 + row) * ldb + kt + c16 * 8;
            uint32_t so = SWZ((uint32_t)(row * 128 + c16 * 16));
            cp16(b0 + OFF_BH + so, Bh + g);
            cp16(b0 + OFF_BL + so, Bl + g);
        }
    };
    stage(0, 0);
    CP_COMMIT();
    for (int t = 0; t < ntiles; t++) {
        if (t + 1 < ntiles) { stage(t + 1, (t + 1) & 1); CP_COMMIT(); CP_WAIT1(); }
        else { CP_WAIT0(); }
        __syncthreads();
        const uint32_t b0 = sb + (t & 1) * STG_STRIDE;
#pragma unroll
        for (int ks = 0; ks < 4; ks++) {
            const uint32_t kb = ks * 32 + lkh * 16;
            uint32_t ah[2][4], al[2][4];
#pragma unroll
            for (int ms = 0; ms < 2; ms++) {
                uint32_t ro = (uint32_t)(wm * 32 + ms * 16 + lrow) * 128 + kb;
                ldsm_x4(ah[ms][0], ah[ms][1], ah[ms][2], ah[ms][3], b0 + OFF_AH + SWZ(ro));
                ldsm_x4(al[ms][0], al[ms][1], al[ms][2], al[ms][3], b0 + OFF_AL + SWZ(ro));
            }
            uint32_t bh[4][2], bl[4][2];
#pragma unroll
            for (int half = 0; half < 2; half++) {
                uint32_t ro = (uint32_t)(wn * 32 + half * 16 + lrow) * 128 + kb;
                uint32_t r0, r1, r2, r3;
                ldsm_x4(r0, r1, r2, r3, b0 + OFF_BH + SWZ(ro));
                bh[half * 2 + 0][0] = r0; bh[half * 2 + 0][1] = r2;
                bh[half * 2 + 1][0] = r1; bh[half * 2 + 1][1] = r3;
                ldsm_x4(r0, r1, r2, r3, b0 + OFF_BL + SWZ(ro));
                bl[half * 2 + 0][0] = r0; bl[half * 2 + 0][1] = r2;
                bl[half * 2 + 1][0] = r1; bl[half * 2 + 1][1] = r3;
            }
#pragma unroll
            for (int ms = 0; ms < 2; ms++)
#pragma unroll
                for (int nb = 0; nb < 4; nb++) {
                    mma16816(acc[ms][nb], ah[ms], bh[nb][0], bh[nb][1]);
                    mma16816(acc[ms][nb], al[ms], bh[nb][0], bh[nb][1]);
                    mma16816(acc[ms][nb], ah[ms], bl[nb][0], bl[nb][1]);
                }
        }
        __syncthreads();
    }

    // ---- epilogue: regs -> padded smem staging -> coalesced global ----
    float* st = (float*)dsm;                     // [128][65] fp32
    {
        const int lr = lane >> 2, lc = (lane & 3) * 2;
#pragma unroll
        for (int ms = 0; ms < 2; ms++)
#pragma unroll
            for (int nb = 0; nb < 4; nb++) {
                int r = wm * 32 + ms * 16 + lr;
                int c = wn * 32 + nb * 8 + lc;
                st[r * 65 + c]            = acc[ms][nb][0];
                st[r * 65 + c + 1]        = acc[ms][nb][1];
                st[(r + 8) * 65 + c]      = acc[ms][nb][2];
                st[(r + 8) * 65 + c + 1]  = acc[ms][nb][3];
            }
    }
    __syncthreads();

    if (EPI == 4) {            // OUT: fp32 + bias, ld 1024
        for (int i = tid; i < MT * NT; i += 256) {
            int row = i >> 6, c = i & 63;
            outF[(long)(m0 + row) * 1024 + n0 + c] = st[row * 65 + c] + bias[n0 + c];
        }
    } else if (EPI == 0) {     // LIN: bias + split, ld 1024
        for (int i = tid; i < MT * NT; i += 256) {
            int row = i >> 6, c = i & 63;
            float v = st[row * 65 + c] + bias[n0 + c];
            long o = (long)(m0 + row) * 1024 + n0 + c;
            __nv_bfloat16 h = __float2bfloat16(v);
            outH[o] = h;
            outL[o] = __float2bfloat16(v - __bfloat162float(h));
        }
    } else {                   // VT: bias + split, transposed per-head [BH,64,S]
        for (int i = tid; i < MT * NT; i += 256) {
            int j = i >> 7, rl = i & 127;
            int r = m0 + rl, cg = n0 + j;
            float v = st[rl * 65 + j] + bias[cg];
            int b = r >> 11, s = r & 2047, hh = cg >> 6, jj = cg & 63;
            long o = ((long)(b * 16 + hh) * 64 + jj) * 2048 + s;
            __nv_bfloat16 h = __float2bfloat16(v);
            outH[o] = h;
            outL[o] = __float2bfloat16(v - __bfloat162float(h));
        }
    }
}

// ---------------------------------------------------------------------------
// Fused scores + softmax + context (R7 structure, cheap pass A).
// Pass A: S via hi*hi ONLY (1 MMA pass) -> row sums of exp.  L's relative
//         error ~1e-4 (errors average over ~750 effective terms per row).
// Pass B: S exact (3-pass split), normalize, store attn once, split P to
//         bf16 hi/lo in regs, O += P @ V^T (3-pass), cross-wn reduce, store ctx.
// smem: Q hi/lo 32K + 2 stages x 32K (A: K hi only; B: K hi/lo + V hi/lo).
// ---------------------------------------------------------------------------
#define FB_QH   0
#define FB_QL   16384
#define FB_ST0  32768           // per stage: KH+0, KL+8192, VH+16384, VL+24576
#define FB_STRIDE 32768
#define FB_PART 98304           // float[2][128]
#define FB_ROWL 99328           // float[128]
#define FB_SM   99840

__global__ void __launch_bounds__(256)
fused_attn_k(const __nv_bfloat16* __restrict__ qh, const __nv_bfloat16* __restrict__ ql,
             const __nv_bfloat16* __restrict__ kh, const __nv_bfloat16* __restrict__ kl,
             const __nv_bfloat16* __restrict__ vth, const __nv_bfloat16* __restrict__ vtl,
             float* __restrict__ attn,
             __nv_bfloat16* __restrict__ ch, __nv_bfloat16* __restrict__ cl)
{
    extern __shared__ uint8_t dsm[];
    const uint32_t sb = smem_u32(dsm);
    const int tid = threadIdx.x, wid = tid >> 5, lane = tid & 31;
    const int wm = wid >> 1, wn = wid & 1;
    const int lrow = lane & 15, lkh = lane >> 4;
    const int lr = lane >> 2, lc = lane & 3;
    const int m0 = blockIdx.x * 128;
    const int z = blockIdx.y;
    const long base = (long)(z >> 4) * 2048L * 1024 + (long)(z & 15) * 64;
    const __nv_bfloat16* qh_h = qh + base;
    const __nv_bfloat16* ql_h = ql + base;
    const __nv_bfloat16* kh_h = kh + base;
    const __nv_bfloat16* kl_h = kl + base;
    const __nv_bfloat16* vh_h = vth + (long)z * 64L * 2048;
    const __nv_bfloat16* vl_h = vtl + (long)z * 64L * 2048;

    float* part  = (float*)(dsm + FB_PART);
    float* row_l = (float*)(dsm + FB_ROWL);

    // Pass A: stage K hi only (8KB per stage)
    auto stage_k_hi = [&](int t, int buf) {
        const uint32_t sd = sb + FB_ST0 + buf * FB_STRIDE;
#pragma unroll
        for (int i = 0; i < 2; i++) {
            int chunk = tid + i * 256;               // 512: 64 rows x 8 chunks
            int row = chunk >> 3, c16 = chunk & 7;
            long g = (long)(t * 64 + row) * 1024 + c16 * 8;
            uint32_t so = SWZ((uint32_t)(row * 128 + c16 * 16));
            if (i == 0) cp16(sd + so, kh_h + g);
            else        cp16(sd + so, kh_h + g);
        }
    };
    // Pass B: stage K hi/lo + V hi/lo (32KB per stage)
    auto stage_kv = [&](int t, int buf) {
        const uint32_t sd = sb + FB_ST0 + buf * FB_STRIDE;
#pragma unroll
        for (int i = 0; i < 2; i++) {
            int chunk = tid + i * 256;
            int row = chunk >> 3, c16 = chunk & 7;
            long g = (long)(t * 64 + row) * 1024 + c16 * 8;
            uint32_t so = SWZ((uint32_t)(row * 128 + c16 * 16));
            cp16(sd + so, kh_h + g);
            cp16(sd + 8192 + so, kl_h + g);
        }
#pragma unroll
        for (int i = 0; i < 2; i++) {
            int chunk = tid + i * 256;               // row = dk 0..63
            int row = chunk >> 3, c16 = chunk & 7;
            long g = (long)row * 2048 + t * 64 + c16 * 8;
            uint32_t so = SWZ((uint32_t)(row * 128 + c16 * 16));
            cp16(sd + 16384 + so, vh_h + g);
            cp16(sd + 24576 + so, vl_h + g);
        }
    };

    // Cheap S tile: hi*hi only (pass A)
    auto compute_tile_hi = [&](int buf, float acc[2][4][4]) {
#pragma unroll
        for (int i = 0; i < 2; i++)
#pragma unroll
            for (int j = 0; j < 4; j++)
#pragma unroll
                for (int r = 0; r < 4; r++) acc[i][j][r] = 0.0f;
        const uint32_t kbh = sb + FB_ST0 + buf * FB_STRIDE;
#pragma unroll
        for (int ks = 0; ks < 4; ks++) {
            const uint32_t kb = ks * 32 + lkh * 16;
            uint32_t ah[2][4];
#pragma unroll
            for (int ms = 0; ms < 2; ms++) {
                uint32_t ro = (uint32_t)(wm * 32 + ms * 16 + lrow) * 128 + kb;
                ldsm_x4(ah[ms][0], ah[ms][1], ah[ms][2], ah[ms][3], sb + FB_QH + SWZ(ro));
            }
            uint32_t bh[4][2];
#pragma unroll
            for (int half = 0; half < 2; half++) {
                uint32_t ro = (uint32_t)(wn * 32 + half * 16 + lrow) * 128 + kb;
                uint32_t r0, r1, r2, r3;
                ldsm_x4(r0, r1, r2, r3, kbh + SWZ(ro));
                bh[half * 2 + 0][0] = r0; bh[half * 2 + 0][1] = r2;
                bh[half * 2 + 1][0] = r1; bh[half * 2 + 1][1] = r3;
            }
#pragma unroll
            for (int ms = 0; ms < 2; ms++)
#pragma unroll
                for (int nb = 0; nb < 4; nb++)
                    mma16816(acc[ms][nb], ah[ms], bh[nb][0], bh[nb][1]);
        }
    };
    // Exact S tile: 3-pass split (pass B)
    auto compute_tile = [&](int buf, float acc[2][4][4]) {
#pragma unroll
        for (int i = 0; i < 2; i++)
#pragma unroll
            for (int j = 0; j < 4; j++)
#pragma unroll
                for (int r = 0; r < 4; r++) acc[i][j][r] = 0.0f;
        const uint32_t kbh = sb + FB_ST0 + buf * FB_STRIDE;
        const uint32_t kbl = kbh + 8192;
#pragma unroll
        for (int ks = 0; ks < 4; ks++) {
            const uint32_t kb = ks * 32 + lkh * 16;
            uint32_t ah[2][4], al[2][4];
#pragma unroll
            for (int ms = 0; ms < 2; ms++) {
                uint32_t ro = (uint32_t)(wm * 32 + ms * 16 + lrow) * 128 + kb;
                ldsm_x4(ah[ms][0], ah[ms][1], ah[ms][2], ah[ms][3], sb + FB_QH + SWZ(ro));
                ldsm_x4(al[ms][0], al[ms][1], al[ms][2], al[ms][3], sb + FB_QL + SWZ(ro));
            }
            uint32_t bh[4][2], bl[4][2];
#pragma unroll
            for (int half = 0; half < 2; half++) {
                uint32_t ro = (uint32_t)(wn * 32 + half * 16 + lrow) * 128 + kb;
                uint32_t r0, r1, r2, r3;
                ldsm_x4(r0, r1, r2, r3, kbh + SWZ(ro));
                bh[half * 2 + 0][0] = r0; bh[half * 2 + 0][1] = r2;
                bh[half * 2 + 1][0] = r1; bh[half * 2 + 1][1] = r3;
                ldsm_x4(r0, r1, r2, r3, kbl + SWZ(ro));
                bl[half * 2 + 0][0] = r0; bl[half * 2 + 0][1] = r2;
                bl[half * 2 + 1][0] = r1; bl[half * 2 + 1][1] = r3;
            }
#pragma unroll
            for (int ms = 0; ms < 2; ms++)
#pragma unroll
                for (int nb = 0; nb < 4; nb++) {
                    mma16816(acc[ms][nb], ah[ms], bh[nb][0], bh[nb][1]);
                    mma16816(acc[ms][nb], al[ms], bh[nb][0], bh[nb][1]);
                    mma16816(acc[ms][nb], ah[ms], bl[nb][0], bl[nb][1]);
                }
        }
    };

    // ---- prologue: q tile + k tile 0 ----
#pragma unroll
    for (int i = 0; i < 4; i++) {
        int chunk = tid + i * 256;                   // 1024: 128 rows x 8
        int row = chunk >> 3, c16 = chunk & 7;
        long g = (long)(m0 + row) * 1024 + c16 * 8;
        uint32_t so = SWZ((uint32_t)(row * 128 + c16 * 16));
        cp16(sb + FB_QH + so, qh_h + g);
        cp16(sb + FB_QL + so, ql_h + g);
    }
    if (tid < 128) row_l[tid] = 0.0f;
    stage_k_hi(0, 0);
    CP_COMMIT();

    float acc[2][4][4];

    // ---- pass A: approximate S (hi*hi), row sums of exp ----
    for (int t = 0; t < 32; t++) {
        if (t + 1 < 32) { stage_k_hi(t + 1, (t + 1) & 1); CP_COMMIT(); CP_WAIT1(); }
        else { CP_WAIT0(); }
        __syncthreads();
        compute_tile_hi(t & 1, acc);
#pragma unroll
        for (int ms = 0; ms < 2; ms++) {
            float s0 = 0.0f, s1 = 0.0f;
#pragma unroll
            for (int nb = 0; nb < 4; nb++) {
                s0 += __expf(acc[ms][nb][0] * 0.125f) + __expf(acc[ms][nb][1] * 0.125f);
                s1 += __expf(acc[ms][nb][2] * 0.125f) + __expf(acc[ms][nb][3] * 0.125f);
            }
            s0 += __shfl_xor_sync(0xffffffffu, s0, 1);
            s0 += __shfl_xor_sync(0xffffffffu, s0, 2);
            s1 += __shfl_xor_sync(0xffffffffu, s1, 1);
            s1 += __shfl_xor_sync(0xffffffffu, s1, 2);
            if (lc == 0) {
                part[wn * 128 + wm * 32 + ms * 16 + lr]     = s0;
                part[wn * 128 + wm * 32 + ms * 16 + 8 + lr] = s1;
            }
        }
        __syncthreads();
        if (tid < 128) row_l[tid] += part[tid] + part[128 + tid];
    }
    __syncthreads();
    float inv[2][2];
#pragma unroll
    for (int ms = 0; ms < 2; ms++) {
        inv[ms][0] = 1.0f / row_l[wm * 32 + ms * 16 + lr];
        inv[ms][1] = 1.0f / row_l[wm * 32 + ms * 16 + 8 + lr];
    }

    // O accumulator: 32 rows x 64 dk per warp (partial over this warp's keys)
    float accO[2][8][4];
#pragma unroll
    for (int ms = 0; ms < 2; ms++)
#pragma unroll
        for (int dn = 0; dn < 8; dn++)
#pragma unroll
            for (int r = 0; r < 4; r++) accO[ms][dn][r] = 0.0f;

    // ---- pass B: exact S, normalize, store attn, O += P @ V^T ----
    stage_kv(0, 0);
    CP_COMMIT();
    for (int t = 0; t < 32; t++) {
        if (t + 1 < 32) { stage_kv(t + 1, (t + 1) & 1); CP_COMMIT(); CP_WAIT1(); }
        else { CP_WAIT0(); }
        __syncthreads();
        compute_tile(t & 1, acc);

        // normalize in place
#pragma unroll
        for (int ms = 0; ms < 2; ms++)
#pragma unroll
            for (int nb = 0; nb < 4; nb++) {
                acc[ms][nb][0] = __expf(acc[ms][nb][0] * 0.125f) * inv[ms][0];
                acc[ms][nb][1] = __expf(acc[ms][nb][1] * 0.125f) * inv[ms][0];
                acc[ms][nb][2] = __expf(acc[ms][nb][2] * 0.125f) * inv[ms][1];
                acc[ms][nb][3] = __expf(acc[ms][nb][3] * 0.125f) * inv[ms][1];
            }

        // store attn (required output, written exactly once)
        const int colb = t * 64 + wn * 32 + lc * 2;
#pragma unroll
        for (int ms = 0; ms < 2; ms++) {
            long rb0 = ((long)z * 2048 + m0 + wm * 32 + ms * 16 + lr) * 2048;
            long rb1 = rb0 + 8L * 2048;
#pragma unroll
            for (int nb = 0; nb < 4; nb++) {
                *(float2*)(attn + rb0 + colb + nb * 8) =
                    make_float2(acc[ms][nb][0], acc[ms][nb][1]);
                *(float2*)(attn + rb1 + colb + nb * 8) =
                    make_float2(acc[ms][nb][2], acc[ms][nb][3]);
            }
        }

        // O += P @ V^T
        const uint32_t vbh = sb + FB_ST0 + (t & 1) * FB_STRIDE + 16384;
        const uint32_t vbl = vbh + 8192;
#pragma unroll
        for (int kh2 = 0; kh2 < 2; kh2++) {
            uint32_t vh[8][2], vl[8][2];
#pragma unroll
            for (int dh = 0; dh < 4; dh++) {
                uint32_t ro = (uint32_t)(dh * 16 + lrow) * 128 +
                              (uint32_t)(wn * 32 + kh2 * 16) * 2 + lkh * 16;
                uint32_t r0, r1, r2, r3;
                ldsm_x4(r0, r1, r2, r3, vbh + SWZ(ro));
                vh[dh * 2 + 0][0] = r0; vh[dh * 2 + 0][1] = r2;
                vh[dh * 2 + 1][0] = r1; vh[dh * 2 + 1][1] = r3;
                ldsm_x4(r0, r1, r2, r3, vbl + SWZ(ro));
                vl[dh * 2 + 0][0] = r0; vl[dh * 2 + 0][1] = r2;
                vl[dh * 2 + 1][0] = r1; vl[dh * 2 + 1][1] = r3;
            }
#pragma unroll
            for (int ms = 0; ms < 2; ms++) {
                const float* c0 = acc[ms][2 * kh2];
                const float* c1 = acc[ms][2 * kh2 + 1];
                uint32_t ph[4], pl[4];
                ph[0] = pack_bf16(c0[0], c0[1]);
                ph[1] = pack_bf16(c0[2], c0[3]);
                ph[2] = pack_bf16(c1[0], c1[1]);
                ph[3] = pack_bf16(c1[2], c1[3]);
                pl[0] = pack_bf16(c0[0] - bf16lo_f(ph[0]), c0[1] - bf16hi_f(ph[0]));
                pl[1] = pack_bf16(c0[2] - bf16lo_f(ph[1]), c0[3] - bf16hi_f(ph[1]));
                pl[2] = pack_bf16(c1[0] - bf16lo_f(ph[2]), c1[1] - bf16hi_f(ph[2]));
                pl[3] = pack_bf16(c1[2] - bf16lo_f(ph[3]), c1[3] - bf16hi_f(ph[3]));
#pragma unroll
                for (int dn = 0; dn < 8; dn++) {
                    mma16816(accO[ms][dn], ph, vh[dn][0], vh[dn][1]);
                    mma16816(accO[ms][dn], pl, vh[dn][0], vh[dn][1]);
                    mma16816(accO[ms][dn], ph, vl[dn][0], vl[dn][1]);
                }
            }
        }
        __syncthreads();
    }

    // ---- ctx epilogue: cross-wn reduce in smem, split store [B,S,D] ----
    float* st = (float*)dsm;                     // [128][65] fp32
    {
        const int lc2 = lc * 2;
        if (wn == 0) {
#pragma unroll
            for (int ms = 0; ms < 2; ms++)
#pragma unroll
                for (int dn = 0; dn < 8; dn++) {
                    int r = wm * 32 + ms * 16 + lr;
                    int c = dn * 8 + lc2;
                    st[r * 65 + c]           = accO[ms][dn][0];
                    st[r * 65 + c + 1]       = accO[ms][dn][1];
                    st[(r + 8) * 65 + c]     = accO[ms][dn][2];
                    st[(r + 8) * 65 + c + 1] = accO[ms][dn][3];
                }
        }
        __syncthreads();
        if (wn == 1) {
#pragma unroll
            for (int ms = 0; ms < 2; ms++)
#pragma unroll
                for (int dn = 0; dn < 8; dn++) {
                    int r = wm * 32 + ms * 16 + lr;
                    int c = dn * 8 + lc2;
                    st[r * 65 + c]           += accO[ms][dn][0];
                    st[r * 65 + c + 1]       += accO[ms][dn][1];
                    st[(r + 8) * 65 + c]     += accO[ms][dn][2];
                    st[(r + 8) * 65 + c + 1] += accO[ms][dn][3];
                }
        }
        __syncthreads();
    }
    {
        const int b = z >> 4, hh = z & 15;
        for (int i = tid; i < 128 * 64; i += 256) {
            int row = i >> 6, c = i & 63;
            float v = st[row * 65 + c];
            long o = (long)((b << 11) + m0 + row) * 1024 + hh * 64 + c;
            __nv_bfloat16 h = __float2bfloat16(v);
            ch[o] = h;
            cl[o] = __float2bfloat16(v - __bfloat162float(h));
        }
    }
}

// ---------------------------------------------------------------------------
extern "C" void kernel_launch(void* const* d_in, const int* in_sizes, int n_in,
                              void* d_out, int out_size)
{
    const float* Q  = (const float*)d_in[0];
    const float* K  = (const float*)d_in[1];
    const float* V  = (const float*)d_in[2];
    const float* Wq = (const float*)d_in[3];
    const float* bq = (const float*)d_in[4];
    const float* Wk = (const float*)d_in[5];
    const float* bk = (const float*)d_in[6];
    const float* Wv = (const float*)d_in[7];
    const float* bv = (const float*)d_in[8];
    const float* Wo = (const float*)d_in[9];
    const float* bo = (const float*)d_in[10];
    float* out = (float*)d_out;

    __nv_bfloat16 *Qh, *Ql, *Kh, *Kl, *Vh, *Vl;
    __nv_bfloat16 *Wqh, *Wql, *Wkh, *Wkl, *Wvh, *Wvl, *Woh, *Wol;
    __nv_bfloat16 *qh, *ql, *kh, *kl, *vth, *vtl, *ch, *cl;
    float* attn_scratch;
    cudaGetSymbolAddress((void**)&Qh, g_Qh);   cudaGetSymbolAddress((void**)&Ql, g_Ql);
    cudaGetSymbolAddress((void**)&Kh, g_Kh);   cudaGetSymbolAddress((void**)&Kl, g_Kl);
    cudaGetSymbolAddress((void**)&Vh, g_Vh);   cudaGetSymbolAddress((void**)&Vl, g_Vl);
    cudaGetSymbolAddress((void**)&Wqh, g_Wqh); cudaGetSymbolAddress((void**)&Wql, g_Wql);
    cudaGetSymbolAddress((void**)&Wkh, g_Wkh); cudaGetSymbolAddress((void**)&Wkl, g_Wkl);
    cudaGetSymbolAddress((void**)&Wvh, g_Wvh); cudaGetSymbolAddress((void**)&Wvl, g_Wvl);
    cudaGetSymbolAddress((void**)&Woh, g_Woh); cudaGetSymbolAddress((void**)&Wol, g_Wol);
    cudaGetSymbolAddress((void**)&qh, g_qh);   cudaGetSymbolAddress((void**)&ql, g_ql);
    cudaGetSymbolAddress((void**)&kh, g_kh);   cudaGetSymbolAddress((void**)&kl, g_kl);
    cudaGetSymbolAddress((void**)&vth, g_vth); cudaGetSymbolAddress((void**)&vtl, g_vtl);
    cudaGetSymbolAddress((void**)&ch, g_ch);   cudaGetSymbolAddress((void**)&cl, g_cl);
    cudaGetSymbolAddress((void**)&attn_scratch, g_attn);

    float* attn = ((long)out_size >= OUT_TOTAL) ? (out + OUT0) : attn_scratch;

    cudaFuncSetAttribute(mma_gemm<0>, cudaFuncAttributeMaxDynamicSharedMemorySize, SM_PIPE);
    cudaFuncSetAttribute(mma_gemm<1>, cudaFuncAttributeMaxDynamicSharedMemorySize, SM_PIPE);
    cudaFuncSetAttribute(mma_gemm<4>, cudaFuncAttributeMaxDynamicSharedMemorySize, SM_PIPE);
    cudaFuncSetAttribute(fused_attn_k, cudaFuncAttributeMaxDynamicSharedMemorySize, FB_SM);

    // 0) One-launch split of all 7 fp32 inputs into bf16 hi/lo
    {
        SplitArgs a;
        a.x[0] = Q;  a.h[0] = Qh;  a.l[0] = Ql;  a.n4[0] = TOKENS * DMODEL / 4;
        a.x[1] = K;  a.h[1] = Kh;  a.l[1] = Kl;  a.n4[1] = TOKENS * DMODEL / 4;
        a.x[2] = V;  a.h[2] = Vh;  a.l[2] = Vl;  a.n4[2] = TOKENS * DMODEL / 4;
        a.x[3] = Wq; a.h[3] = Wqh; a.l[3] = Wql; a.n4[3] = DMODEL * DMODEL / 4;
        a.x[4] = Wk; a.h[4] = Wkh; a.l[4] = Wkl; a.n4[4] = DMODEL * DMODEL / 4;
        a.x[5] = Wv; a.h[5] = Wvh; a.l[5] = Wvl; a.n4[5] = DMODEL * DMODEL / 4;
        a.x[6] = Wo; a.h[6] = Woh; a.l[6] = Wol; a.n4[6] = DMODEL * DMODEL / 4;
        dim3 gs((TOKENS * DMODEL / 4 + 255) / 256, 7, 1);
        split_all<<<gs, 256>>>(a);
    }

    // 1-3) Projections: [4096,1024] @ W^T + b (pipelined)
    dim3 gp(DMODEL / NT, TOKENS / MT, 1);                       // (16, 32)
    mma_gemm<0><<<gp, 256, SM_PIPE>>>(Qh, Ql, Wqh, Wql, bq, nullptr, qh, ql,
                                      DMODEL, DMODEL, DMODEL);
    mma_gemm<0><<<gp, 256, SM_PIPE>>>(Kh, Kl, Wkh, Wkl, bk, nullptr, kh, kl,
                                      DMODEL, DMODEL, DMODEL);
    mma_gemm<1><<<gp, 256, SM_PIPE>>>(Vh, Vl, Wvh, Wvl, bv, nullptr, vth, vtl,
                                      DMODEL, DMODEL, DMODEL);

    // 4) Fused scores + softmax + context (cheap pass A, exact pass B)
    dim3 gf(SEQ / 128, BH, 1);                                  // (16, 32)
    fused_attn_k<<<gf, 256, FB_SM>>>(qh, ql, kh, kl, vth, vtl, attn, ch, cl);

    // 5) Output projection: ctx @ Wo^T + bo -> out fp32 (pipelined)
    mma_gemm<4><<<gp, 256, SM_PIPE>>>(ch, cl, Woh, Wol, bo, out, nullptr, nullptr,
                                      DMODEL, DMODEL, DMODEL);

    (void)n_in; (void)in_sizes;
}

// round 10
// speedup vs baseline: 1.4153x; 1.0668x over previous
#include <cuda_runtime.h>
#include <cuda_bf16.h>
#include <cuda_fp16.h>
#include <cstdint>

// ---------------------------------------------------------------------------
// Problem constants
// ---------------------------------------------------------------------------
#define BATCH   2
#define SEQ     2048
#define DMODEL  1024
#define NHEAD   16
#define DK      64
#define BH      (BATCH * NHEAD)              // 32
#define TOKENS  (BATCH * SEQ)                // 4096
#define OUT0    (TOKENS * DMODEL)            // 4,194,304
#define ATTN_N  ((long)BH * SEQ * SEQ)       // 134,217,728
#define OUT_TOTAL (OUT0 + ATTN_N)

// ---------------------------------------------------------------------------
// Scratch (static device arrays; no cudaMalloc anywhere)
// bf16 planes feed the projections (proven 3-pass path);
// fp16 planes feed the fused attention kernel.
// ---------------------------------------------------------------------------
__device__ __nv_bfloat16 g_Qh[TOKENS * DMODEL], g_Ql[TOKENS * DMODEL];
__device__ __nv_bfloat16 g_Kh[TOKENS * DMODEL], g_Kl[TOKENS * DMODEL];
__device__ __nv_bfloat16 g_Vh[TOKENS * DMODEL], g_Vl[TOKENS * DMODEL];
__device__ __nv_bfloat16 g_Wqh[DMODEL * DMODEL], g_Wql[DMODEL * DMODEL];
__device__ __nv_bfloat16 g_Wkh[DMODEL * DMODEL], g_Wkl[DMODEL * DMODEL];
__device__ __nv_bfloat16 g_Wvh[DMODEL * DMODEL], g_Wvl[DMODEL * DMODEL];
__device__ __nv_bfloat16 g_Woh[DMODEL * DMODEL], g_Wol[DMODEL * DMODEL];
__device__ __half g_qh[TOKENS * DMODEL], g_ql[TOKENS * DMODEL];     // [B,S,H*64] fp16
__device__ __half g_kh[TOKENS * DMODEL], g_kl[TOKENS * DMODEL];     // [B,S,H*64] fp16
__device__ __half g_vth[BH * DK * SEQ],  g_vtl[BH * DK * SEQ];      // [BH,64,S] fp16
__device__ __nv_bfloat16 g_ch[TOKENS * DMODEL], g_cl[TOKENS * DMODEL];  // ctx bf16
__device__ float g_attn[ATTN_N];                 // fallback if d_out lacks attn

// ---------------------------------------------------------------------------
// Helpers
// ---------------------------------------------------------------------------
__device__ __forceinline__ uint32_t smem_u32(const void* p) {
    uint32_t a;
    asm("{ .reg .u64 t; cvta.to.shared.u64 t, %1; cvt.u32.u64 %0, t; }"
        : "=r"(a) : "l"(p));
    return a;
}
#define SWZ(off) ((off) ^ (((off) >> 3) & 0x70))

__device__ __forceinline__ void ldsm_x4(uint32_t& r0, uint32_t& r1,
                                        uint32_t& r2, uint32_t& r3, uint32_t a) {
    asm volatile("ldmatrix.sync.aligned.m8n8.x4.shared.b16 {%0,%1,%2,%3}, [%4];"
                 : "=r"(r0), "=r"(r1), "=r"(r2), "=r"(r3) : "r"(a));
}
// bf16 mma (projections)
__device__ __forceinline__ void mma_bf16(float* c, const uint32_t* a,
                                         uint32_t b0, uint32_t b1) {
    asm volatile(
        "mma.sync.aligned.m16n8k16.row.col.f32.bf16.bf16.f32 "
        "{%0,%1,%2,%3}, {%4,%5,%6,%7}, {%8,%9}, {%0,%1,%2,%3};"
        : "+f"(c[0]), "+f"(c[1]), "+f"(c[2]), "+f"(c[3])
        : "r"(a[0]), "r"(a[1]), "r"(a[2]), "r"(a[3]), "r"(b0), "r"(b1));
}
// fp16 mma (fused attention)
__device__ __forceinline__ void mma_f16(float* c, const uint32_t* a,
                                        uint32_t b0, uint32_t b1) {
    asm volatile(
        "mma.sync.aligned.m16n8k16.row.col.f32.f16.f16.f32 "
        "{%0,%1,%2,%3}, {%4,%5,%6,%7}, {%8,%9}, {%0,%1,%2,%3};"
        : "+f"(c[0]), "+f"(c[1]), "+f"(c[2]), "+f"(c[3])
        : "r"(a[0]), "r"(a[1]), "r"(a[2]), "r"(a[3]), "r"(b0), "r"(b1));
}
__device__ __forceinline__ void cp16(uint32_t dst, const void* src) {
    asm volatile("cp.async.cg.shared.global [%0], [%1], 16;"
                 :: "r"(dst), "l"(src) : "memory");
}
#define CP_COMMIT() asm volatile("cp.async.commit_group;" ::: "memory")
#define CP_WAIT1()  asm volatile("cp.async.wait_group 1;" ::: "memory")
#define CP_WAIT0()  asm volatile("cp.async.wait_group 0;" ::: "memory")

// pack two fp32 -> f16x2 register (first arg in low half)
__device__ __forceinline__ uint32_t pack_half(float lo, float hi) {
    uint32_t r;
    asm("cvt.rn.f16x2.f32 %0, %1, %2;" : "=r"(r) : "f"(hi), "f"(lo));
    return r;
}

// ---------------------------------------------------------------------------
// One-launch fp32 -> bf16 hi/lo split over all 7 inputs (grid.y = segment)
// ---------------------------------------------------------------------------
struct SplitArgs {
    const float* x[7];
    __nv_bfloat16* h[7];
    __nv_bfloat16* l[7];
    int n4[7];                 // float4 group count per segment
};

__global__ void __launch_bounds__(256)
split_all(SplitArgs a)
{
    const int seg = blockIdx.y;
    const int i = blockIdx.x * 256 + threadIdx.x;
    if (i >= a.n4[seg]) return;
    float4 v = ((const float4*)a.x[seg])[i];
    __nv_bfloat16 h0 = __float2bfloat16(v.x), h1 = __float2bfloat16(v.y);
    __nv_bfloat16 h2 = __float2bfloat16(v.z), h3 = __float2bfloat16(v.w);
    float l0 = v.x - __bfloat162float(h0), l1 = v.y - __bfloat162float(h1);
    float l2 = v.z - __bfloat162float(h2), l3 = v.w - __bfloat162float(h3);
    uint2 hv, lv;
    hv.x = (uint32_t)__bfloat16_as_ushort(h0) | ((uint32_t)__bfloat16_as_ushort(h1) << 16);
    hv.y = (uint32_t)__bfloat16_as_ushort(h2) | ((uint32_t)__bfloat16_as_ushort(h3) << 16);
    lv.x = (uint32_t)__bfloat16_as_ushort(__float2bfloat16(l0)) |
           ((uint32_t)__bfloat16_as_ushort(__float2bfloat16(l1)) << 16);
    lv.y = (uint32_t)__bfloat16_as_ushort(__float2bfloat16(l2)) |
           ((uint32_t)__bfloat16_as_ushort(__float2bfloat16(l3)) << 16);
    ((uint2*)a.h[seg])[i] = hv;
    ((uint2*)a.l[seg])[i] = lv;
}

// ---------------------------------------------------------------------------
// mma.sync split-bf16 GEMM (pre-split bf16 operands, cp.async 2-stage).
// Tile M=128, N=64, K-tile=64; 256 threads (8 warps, 4x2 grid, 32x32/warp).
// C = A @ B^T, K-major SW128 smem tiles.  3 HMMA passes per fragment.
// EPI:  0 LIN (bias + fp16 hi/lo split store, ld 1024)  [Q/K projections]
//       1 VT  (bias + fp16 split, transposed per-head)  [V projection]
//       4 OUT (bias, fp32 store ld 1024)                [output projection]
// ---------------------------------------------------------------------------
#define MT 128
#define NT 64
#define KT 64
#define STG_STRIDE 49152
#define OFF_AH 0
#define OFF_AL 16384
#define OFF_BH 32768
#define OFF_BL 40960
#define SM_PIPE  98304

template <int EPI>
__global__ void __launch_bounds__(256)
mma_gemm(const __nv_bfloat16* __restrict__ Ah, const __nv_bfloat16* __restrict__ Al,
         const __nv_bfloat16* __restrict__ Bh, const __nv_bfloat16* __restrict__ Bl,
         const float* __restrict__ bias, float* __restrict__ outF,
         __half* __restrict__ outH, __half* __restrict__ outL,
         int K, int lda, int ldb)
{
    extern __shared__ uint8_t dsm[];
    const uint32_t sb = smem_u32(dsm);
    const int tid = threadIdx.x, wid = tid >> 5, lane = tid & 31;
    const int wm = wid >> 1, wn = wid & 1;
    const int n0 = blockIdx.x * NT, m0 = blockIdx.y * MT;

    float acc[2][4][4];
#pragma unroll
    for (int i = 0; i < 2; i++)
#pragma unroll
        for (int j = 0; j < 4; j++)
#pragma unroll
            for (int r = 0; r < 4; r++) acc[i][j][r] = 0.0f;

    const int lrow = lane & 15, lkh = lane >> 4;

    const int ntiles = K / KT;
    auto stage = [&](int kti, int buf) {
        const uint32_t b0 = sb + buf * STG_STRIDE;
        const int kt = kti * KT;
#pragma unroll
        for (int i = 0; i < 4; i++) {
            int chunk = tid + i * 256;
            int row = chunk >> 3, c16 = chunk & 7;
            long g = (long)(m0 + row) * lda + kt + c16 * 8;
            uint32_t so = SWZ((uint32_t)(row * 128 + c16 * 16));
            cp16(b0 + OFF_AH + so, Ah + g);
            cp16(b0 + OFF_AL + so, Al + g);
        }
#pragma unroll
        for (int i = 0; i < 2; i++) {
            int chunk = tid + i * 256;
            int row = chunk >> 3, c16 = chunk & 7;
            long g = (long)(n0 + row) * ldb + kt + c16 * 8;
            uint32_t so = SWZ((uint32_t)(row * 128 + c16 * 16));
            cp16(b0 + OFF_BH + so, Bh + g);
            cp16(b0 + OFF_BL + so, Bl + g);
        }
    };
    stage(0, 0);
    CP_COMMIT();
    for (int t = 0; t < ntiles; t++) {
        if (t + 1 < ntiles) { stage(t + 1, (t + 1) & 1); CP_COMMIT(); CP_WAIT1(); }
        else { CP_WAIT0(); }
        __syncthreads();
        const uint32_t b0 = sb + (t & 1) * STG_STRIDE;
#pragma unroll
        for (int ks = 0; ks < 4; ks++) {
            const uint32_t kb = ks * 32 + lkh * 16;
            uint32_t ah[2][4], al[2][4];
#pragma unroll
            for (int ms = 0; ms < 2; ms++) {
                uint32_t ro = (uint32_t)(wm * 32 + ms * 16 + lrow) * 128 + kb;
                ldsm_x4(ah[ms][0], ah[ms][1], ah[ms][2], ah[ms][3], b0 + OFF_AH + SWZ(ro));
                ldsm_x4(al[ms][0], al[ms][1], al[ms][2], al[ms][3], b0 + OFF_AL + SWZ(ro));
            }
            uint32_t bh[4][2], bl[4][2];
#pragma unroll
            for (int half = 0; half < 2; half++) {
                uint32_t ro = (uint32_t)(wn * 32 + half * 16 + lrow) * 128 + kb;
                uint32_t r0, r1, r2, r3;
                ldsm_x4(r0, r1, r2, r3, b0 + OFF_BH + SWZ(ro));
                bh[half * 2 + 0][0] = r0; bh[half * 2 + 0][1] = r2;
                bh[half * 2 + 1][0] = r1; bh[half * 2 + 1][1] = r3;
                ldsm_x4(r0, r1, r2, r3, b0 + OFF_BL + SWZ(ro));
                bl[half * 2 + 0][0] = r0; bl[half * 2 + 0][1] = r2;
                bl[half * 2 + 1][0] = r1; bl[half * 2 + 1][1] = r3;
            }
#pragma unroll
            for (int ms = 0; ms < 2; ms++)
#pragma unroll
                for (int nb = 0; nb < 4; nb++) {
                    mma_bf16(acc[ms][nb], ah[ms], bh[nb][0], bh[nb][1]);
                    mma_bf16(acc[ms][nb], al[ms], bh[nb][0], bh[nb][1]);
                    mma_bf16(acc[ms][nb], ah[ms], bl[nb][0], bl[nb][1]);
                }
        }
        __syncthreads();
    }

    // ---- epilogue: regs -> padded smem staging -> coalesced global ----
    float* st = (float*)dsm;                     // [128][65] fp32
    {
        const int lr = lane >> 2, lc = (lane & 3) * 2;
#pragma unroll
        for (int ms = 0; ms < 2; ms++)
#pragma unroll
            for (int nb = 0; nb < 4; nb++) {
                int r = wm * 32 + ms * 16 + lr;
                int c = wn * 32 + nb * 8 + lc;
                st[r * 65 + c]            = acc[ms][nb][0];
                st[r * 65 + c + 1]        = acc[ms][nb][1];
                st[(r + 8) * 65 + c]      = acc[ms][nb][2];
                st[(r + 8) * 65 + c + 1]  = acc[ms][nb][3];
            }
    }
    __syncthreads();

    if (EPI == 4) {            // OUT: fp32 + bias, ld 1024
        for (int i = tid; i < MT * NT; i += 256) {
            int row = i >> 6, c = i & 63;
            outF[(long)(m0 + row) * 1024 + n0 + c] = st[row * 65 + c] + bias[n0 + c];
        }
    } else if (EPI == 0) {     // LIN: bias + fp16 hi/lo split, ld 1024
        for (int i = tid; i < MT * NT; i += 256) {
            int row = i >> 6, c = i & 63;
            float v = st[row * 65 + c] + bias[n0 + c];
            long o = (long)(m0 + row) * 1024 + n0 + c;
            __half h = __float2half_rn(v);
            outH[o] = h;
            outL[o] = __float2half_rn(v - __half2float(h));
        }
    } else {                   // VT: bias + fp16 split, transposed [BH,64,S]
        for (int i = tid; i < MT * NT; i += 256) {
            int j = i >> 7, rl = i & 127;
            int r = m0 + rl, cg = n0 + j;
            float v = st[rl * 65 + j] + bias[cg];
            int b = r >> 11, s = r & 2047, hh = cg >> 6, jj = cg & 63;
            long o = ((long)(b * 16 + hh) * 64 + jj) * 2048 + s;
            __half h = __float2half_rn(v);
            outH[o] = h;
            outL[o] = __float2half_rn(v - __half2float(h));
        }
    }
}

// ---------------------------------------------------------------------------
// Fused scores + softmax + context — fp16 operand version.
// Pass A: S via qh*kh fp16 1-pass -> row sums of exp (L err ~5e-5 max).
// Pass B: S exact (3-pass fp16 split), normalize, store attn once,
//         P -> single fp16 plane, O += P@(Vh + Vl) (2 MMA passes),
//         cross-wn reduce, bf16-split ctx store.
// ---------------------------------------------------------------------------
#define FB_QH   0
#define FB_QL   16384
#define FB_ST0  32768           // per stage: KH+0, KL+8192, VH+16384, VL+24576
#define FB_STRIDE 32768
#define FB_PART 98304           // float[2][128]
#define FB_ROWL 99328           // float[128]
#define FB_SM   99840

__global__ void __launch_bounds__(256)
fused_attn_k(const __half* __restrict__ qh, const __half* __restrict__ ql,
             const __half* __restrict__ kh, const __half* __restrict__ kl,
             const __half* __restrict__ vth, const __half* __restrict__ vtl,
             float* __restrict__ attn,
             __nv_bfloat16* __restrict__ ch, __nv_bfloat16* __restrict__ cl)
{
    extern __shared__ uint8_t dsm[];
    const uint32_t sb = smem_u32(dsm);
    const int tid = threadIdx.x, wid = tid >> 5, lane = tid & 31;
    const int wm = wid >> 1, wn = wid & 1;
    const int lrow = lane & 15, lkh = lane >> 4;
    const int lr = lane >> 2, lc = lane & 3;
    const int m0 = blockIdx.x * 128;
    const int z = blockIdx.y;
    const long base = (long)(z >> 4) * 2048L * 1024 + (long)(z & 15) * 64;
    const __half* qh_h = qh + base;
    const __half* ql_h = ql + base;
    const __half* kh_h = kh + base;
    const __half* kl_h = kl + base;
    const __half* vh_h = vth + (long)z * 64L * 2048;
    const __half* vl_h = vtl + (long)z * 64L * 2048;

    float* part  = (float*)(dsm + FB_PART);
    float* row_l = (float*)(dsm + FB_ROWL);

    // Pass A: stage K hi only (8KB per stage)
    auto stage_k_hi = [&](int t, int buf) {
        const uint32_t sd = sb + FB_ST0 + buf * FB_STRIDE;
#pragma unroll
        for (int i = 0; i < 2; i++) {
            int chunk = tid + i * 256;               // 512: 64 rows x 8 chunks
            int row = chunk >> 3, c16 = chunk & 7;
            long g = (long)(t * 64 + row) * 1024 + c16 * 8;
            uint32_t so = SWZ((uint32_t)(row * 128 + c16 * 16));
            cp16(sd + so, kh_h + g);
        }
    };
    // Pass B: stage K hi/lo + V hi/lo (32KB per stage)
    auto stage_kv = [&](int t, int buf) {
        const uint32_t sd = sb + FB_ST0 + buf * FB_STRIDE;
#pragma unroll
        for (int i = 0; i < 2; i++) {
            int chunk = tid + i * 256;
            int row = chunk >> 3, c16 = chunk & 7;
            long g = (long)(t * 64 + row) * 1024 + c16 * 8;
            uint32_t so = SWZ((uint32_t)(row * 128 + c16 * 16));
            cp16(sd + so, kh_h + g);
            cp16(sd + 8192 + so, kl_h + g);
        }
#pragma unroll
        for (int i = 0; i < 2; i++) {
            int chunk = tid + i * 256;               // row = dk 0..63
            int row = chunk >> 3, c16 = chunk & 7;
            long g = (long)row * 2048 + t * 64 + c16 * 8;
            uint32_t so = SWZ((uint32_t)(row * 128 + c16 * 16));
            cp16(sd + 16384 + so, vh_h + g);
            cp16(sd + 24576 + so, vl_h + g);
        }
    };

    // Cheap S tile: hi*hi only (pass A), fp16
    auto compute_tile_hi = [&](int buf, float acc[2][4][4]) {
#pragma unroll
        for (int i = 0; i < 2; i++)
#pragma unroll
            for (int j = 0; j < 4; j++)
#pragma unroll
                for (int r = 0; r < 4; r++) acc[i][j][r] = 0.0f;
        const uint32_t kbh = sb + FB_ST0 + buf * FB_STRIDE;
#pragma unroll
        for (int ks = 0; ks < 4; ks++) {
            const uint32_t kb = ks * 32 + lkh * 16;
            uint32_t ah[2][4];
#pragma unroll
            for (int ms = 0; ms < 2; ms++) {
                uint32_t ro = (uint32_t)(wm * 32 + ms * 16 + lrow) * 128 + kb;
                ldsm_x4(ah[ms][0], ah[ms][1], ah[ms][2], ah[ms][3], sb + FB_QH + SWZ(ro));
            }
            uint32_t bh[4][2];
#pragma unroll
            for (int half = 0; half < 2; half++) {
                uint32_t ro = (uint32_t)(wn * 32 + half * 16 + lrow) * 128 + kb;
                uint32_t r0, r1, r2, r3;
                ldsm_x4(r0, r1, r2, r3, kbh + SWZ(ro));
                bh[half * 2 + 0][0] = r0; bh[half * 2 + 0][1] = r2;
                bh[half * 2 + 1][0] = r1; bh[half * 2 + 1][1] = r3;
            }
#pragma unroll
            for (int ms = 0; ms < 2; ms++)
#pragma unroll
                for (int nb = 0; nb < 4; nb++)
                    mma_f16(acc[ms][nb], ah[ms], bh[nb][0], bh[nb][1]);
        }
    };
    // Exact S tile: 3-pass fp16 split (pass B)
    auto compute_tile = [&](int buf, float acc[2][4][4]) {
#pragma unroll
        for (int i = 0; i < 2; i++)
#pragma unroll
            for (int j = 0; j < 4; j++)
#pragma unroll
                for (int r = 0; r < 4; r++) acc[i][j][r] = 0.0f;
        const uint32_t kbh = sb + FB_ST0 + buf * FB_STRIDE;
        const uint32_t kbl = kbh + 8192;
#pragma unroll
        for (int ks = 0; ks < 4; ks++) {
            const uint32_t kb = ks * 32 + lkh * 16;
            uint32_t ah[2][4], al[2][4];
#pragma unroll
            for (int ms = 0; ms < 2; ms++) {
                uint32_t ro = (uint32_t)(wm * 32 + ms * 16 + lrow) * 128 + kb;
                ldsm_x4(ah[ms][0], ah[ms][1], ah[ms][2], ah[ms][3], sb + FB_QH + SWZ(ro));
                ldsm_x4(al[ms][0], al[ms][1], al[ms][2], al[ms][3], sb + FB_QL + SWZ(ro));
            }
            uint32_t bh[4][2], bl[4][2];
#pragma unroll
            for (int half = 0; half < 2; half++) {
                uint32_t ro = (uint32_t)(wn * 32 + half * 16 + lrow) * 128 + kb;
                uint32_t r0, r1, r2, r3;
                ldsm_x4(r0, r1, r2, r3, kbh + SWZ(ro));
                bh[half * 2 + 0][0] = r0; bh[half * 2 + 0][1] = r2;
                bh[half * 2 + 1][0] = r1; bh[half * 2 + 1][1] = r3;
                ldsm_x4(r0, r1, r2, r3, kbl + SWZ(ro));
                bl[half * 2 + 0][0] = r0; bl[half * 2 + 0][1] = r2;
                bl[half * 2 + 1][0] = r1; bl[half * 2 + 1][1] = r3;
            }
#pragma unroll
            for (int ms = 0; ms < 2; ms++)
#pragma unroll
                for (int nb = 0; nb < 4; nb++) {
                    mma_f16(acc[ms][nb], ah[ms], bh[nb][0], bh[nb][1]);
                    mma_f16(acc[ms][nb], al[ms], bh[nb][0], bh[nb][1]);
                    mma_f16(acc[ms][nb], ah[ms], bl[nb][0], bl[nb][1]);
                }
        }
    };

    // ---- prologue: q tile + k tile 0 ----
#pragma unroll
    for (int i = 0; i < 4; i++) {
        int chunk = tid + i * 256;                   // 1024: 128 rows x 8
        int row = chunk >> 3, c16 = chunk & 7;
        long g = (long)(m0 + row) * 1024 + c16 * 8;
        uint32_t so = SWZ((uint32_t)(row * 128 + c16 * 16));
        cp16(sb + FB_QH + so, qh_h + g);
        cp16(sb + FB_QL + so, ql_h + g);
    }
    if (tid < 128) row_l[tid] = 0.0f;
    stage_k_hi(0, 0);
    CP_COMMIT();

    float acc[2][4][4];

    // ---- pass A: approximate S (fp16 hi*hi), row sums of exp ----
    for (int t = 0; t < 32; t++) {
        if (t + 1 < 32) { stage_k_hi(t + 1, (t + 1) & 1); CP_COMMIT(); CP_WAIT1(); }
        else { CP_WAIT0(); }
        __syncthreads();
        compute_tile_hi(t & 1, acc);
#pragma unroll
        for (int ms = 0; ms < 2; ms++) {
            float s0 = 0.0f, s1 = 0.0f;
#pragma unroll
            for (int nb = 0; nb < 4; nb++) {
                s0 += __expf(acc[ms][nb][0] * 0.125f) + __expf(acc[ms][nb][1] * 0.125f);
                s1 += __expf(acc[ms][nb][2] * 0.125f) + __expf(acc[ms][nb][3] * 0.125f);
            }
            s0 += __shfl_xor_sync(0xffffffffu, s0, 1);
            s0 += __shfl_xor_sync(0xffffffffu, s0, 2);
            s1 += __shfl_xor_sync(0xffffffffu, s1, 1);
            s1 += __shfl_xor_sync(0xffffffffu, s1, 2);
            if (lc == 0) {
                part[wn * 128 + wm * 32 + ms * 16 + lr]     = s0;
                part[wn * 128 + wm * 32 + ms * 16 + 8 + lr] = s1;
            }
        }
        __syncthreads();
        if (tid < 128) row_l[tid] += part[tid] + part[128 + tid];
    }
    __syncthreads();
    float inv[2][2];
#pragma unroll
    for (int ms = 0; ms < 2; ms++) {
        inv[ms][0] = 1.0f / row_l[wm * 32 + ms * 16 + lr];
        inv[ms][1] = 1.0f / row_l[wm * 32 + ms * 16 + 8 + lr];
    }

    // O accumulator: 32 rows x 64 dk per warp (partial over this warp's keys)
    float accO[2][8][4];
#pragma unroll
    for (int ms = 0; ms < 2; ms++)
#pragma unroll
        for (int dn = 0; dn < 8; dn++)
#pragma unroll
            for (int r = 0; r < 4; r++) accO[ms][dn][r] = 0.0f;

    // ---- pass B: exact S, normalize, store attn, O += P @ (Vh + Vl) ----
    stage_kv(0, 0);
    CP_COMMIT();
    for (int t = 0; t < 32; t++) {
        if (t + 1 < 32) { stage_kv(t + 1, (t + 1) & 1); CP_COMMIT(); CP_WAIT1(); }
        else { CP_WAIT0(); }
        __syncthreads();
        compute_tile(t & 1, acc);

        // normalize in place
#pragma unroll
        for (int ms = 0; ms < 2; ms++)
#pragma unroll
            for (int nb = 0; nb < 4; nb++) {
                acc[ms][nb][0] = __expf(acc[ms][nb][0] * 0.125f) * inv[ms][0];
                acc[ms][nb][1] = __expf(acc[ms][nb][1] * 0.125f) * inv[ms][0];
                acc[ms][nb][2] = __expf(acc[ms][nb][2] * 0.125f) * inv[ms][1];
                acc[ms][nb][3] = __expf(acc[ms][nb][3] * 0.125f) * inv[ms][1];
            }

        // store attn (required output, written exactly once)
        const int colb = t * 64 + wn * 32 + lc * 2;
#pragma unroll
        for (int ms = 0; ms < 2; ms++) {
            long rb0 = ((long)z * 2048 + m0 + wm * 32 + ms * 16 + lr) * 2048;
            long rb1 = rb0 + 8L * 2048;
#pragma unroll
            for (int nb = 0; nb < 4; nb++) {
                *(float2*)(attn + rb0 + colb + nb * 8) =
                    make_float2(acc[ms][nb][0], acc[ms][nb][1]);
                *(float2*)(attn + rb1 + colb + nb * 8) =
                    make_float2(acc[ms][nb][2], acc[ms][nb][3]);
            }
        }

        // O += P @ V^T  (P single fp16 plane; V hi + lo planes: 2 passes)
        const uint32_t vbh = sb + FB_ST0 + (t & 1) * FB_STRIDE + 16384;
        const uint32_t vbl = vbh + 8192;
#pragma unroll
        for (int kh2 = 0; kh2 < 2; kh2++) {
            uint32_t vh[8][2], vl[8][2];
#pragma unroll
            for (int dh = 0; dh < 4; dh++) {
                uint32_t ro = (uint32_t)(dh * 16 + lrow) * 128 +
                              (uint32_t)(wn * 32 + kh2 * 16) * 2 + lkh * 16;
                uint32_t r0, r1, r2, r3;
                ldsm_x4(r0, r1, r2, r3, vbh + SWZ(ro));
                vh[dh * 2 + 0][0] = r0; vh[dh * 2 + 0][1] = r2;
                vh[dh * 2 + 1][0] = r1; vh[dh * 2 + 1][1] = r3;
                ldsm_x4(r0, r1, r2, r3, vbl + SWZ(ro));
                vl[dh * 2 + 0][0] = r0; vl[dh * 2 + 0][1] = r2;
                vl[dh * 2 + 1][0] = r1; vl[dh * 2 + 1][1] = r3;
            }
#pragma unroll
            for (int ms = 0; ms < 2; ms++) {
                const float* c0 = acc[ms][2 * kh2];
                const float* c1 = acc[ms][2 * kh2 + 1];
                uint32_t ph[4];
                ph[0] = pack_half(c0[0], c0[1]);
                ph[1] = pack_half(c0[2], c0[3]);
                ph[2] = pack_half(c1[0], c1[1]);
                ph[3] = pack_half(c1[2], c1[3]);
#pragma unroll
                for (int dn = 0; dn < 8; dn++) {
                    mma_f16(accO[ms][dn], ph, vh[dn][0], vh[dn][1]);
                    mma_f16(accO[ms][dn], ph, vl[dn][0], vl[dn][1]);
                }
            }
        }
        __syncthreads();
    }

    // ---- ctx epilogue: cross-wn reduce in smem, bf16 split store [B,S,D] ----
    float* st = (float*)dsm;                     // [128][65] fp32
    {
        const int lc2 = lc * 2;
        if (wn == 0) {
#pragma unroll
            for (int ms = 0; ms < 2; ms++)
#pragma unroll
                for (int dn = 0; dn < 8; dn++) {
                    int r = wm * 32 + ms * 16 + lr;
                    int c = dn * 8 + lc2;
                    st[r * 65 + c]           = accO[ms][dn][0];
                    st[r * 65 + c + 1]       = accO[ms][dn][1];
                    st[(r + 8) * 65 + c]     = accO[ms][dn][2];
                    st[(r + 8) * 65 + c + 1] = accO[ms][dn][3];
                }
        }
        __syncthreads();
        if (wn == 1) {
#pragma unroll
            for (int ms = 0; ms < 2; ms++)
#pragma unroll
                for (int dn = 0; dn < 8; dn++) {
                    int r = wm * 32 + ms * 16 + lr;
                    int c = dn * 8 + lc2;
                    st[r * 65 + c]           += accO[ms][dn][0];
                    st[r * 65 + c + 1]       += accO[ms][dn][1];
                    st[(r + 8) * 65 + c]     += accO[ms][dn][2];
                    st[(r + 8) * 65 + c + 1] += accO[ms][dn][3];
                }
        }
        __syncthreads();
    }
    {
        const int b = z >> 4, hh = z & 15;
        for (int i = tid; i < 128 * 64; i += 256) {
            int row = i >> 6, c = i & 63;
            float v = st[row * 65 + c];
            long o = (long)((b << 11) + m0 + row) * 1024 + hh * 64 + c;
            __nv_bfloat16 h = __float2bfloat16(v);
            ch[o] = h;
            cl[o] = __float2bfloat16(v - __bfloat162float(h));
        }
    }
}

// ---------------------------------------------------------------------------
extern "C" void kernel_launch(void* const* d_in, const int* in_sizes, int n_in,
                              void* d_out, int out_size)
{
    const float* Q  = (const float*)d_in[0];
    const float* K  = (const float*)d_in[1];
    const float* V  = (const float*)d_in[2];
    const float* Wq = (const float*)d_in[3];
    const float* bq = (const float*)d_in[4];
    const float* Wk = (const float*)d_in[5];
    const float* bk = (const float*)d_in[6];
    const float* Wv = (const float*)d_in[7];
    const float* bv = (const float*)d_in[8];
    const float* Wo = (const float*)d_in[9];
    const float* bo = (const float*)d_in[10];
    float* out = (float*)d_out;

    __nv_bfloat16 *Qh, *Ql, *Kh, *Kl, *Vh, *Vl;
    __nv_bfloat16 *Wqh, *Wql, *Wkh, *Wkl, *Wvh, *Wvl, *Woh, *Wol;
    __half *qh, *ql, *kh, *kl, *vth, *vtl;
    __nv_bfloat16 *ch, *cl;
    float* attn_scratch;
    cudaGetSymbolAddress((void**)&Qh, g_Qh);   cudaGetSymbolAddress((void**)&Ql, g_Ql);
    cudaGetSymbolAddress((void**)&Kh, g_Kh);   cudaGetSymbolAddress((void**)&Kl, g_Kl);
    cudaGetSymbolAddress((void**)&Vh, g_Vh);   cudaGetSymbolAddress((void**)&Vl, g_Vl);
    cudaGetSymbolAddress((void**)&Wqh, g_Wqh); cudaGetSymbolAddress((void**)&Wql, g_Wql);
    cudaGetSymbolAddress((void**)&Wkh, g_Wkh); cudaGetSymbolAddress((void**)&Wkl, g_Wkl);
    cudaGetSymbolAddress((void**)&Wvh, g_Wvh); cudaGetSymbolAddress((void**)&Wvl, g_Wvl);
    cudaGetSymbolAddress((void**)&Woh, g_Woh); cudaGetSymbolAddress((void**)&Wol, g_Wol);
    cudaGetSymbolAddress((void**)&qh, g_qh);   cudaGetSymbolAddress((void**)&ql, g_ql);
    cudaGetSymbolAddress((void**)&kh, g_kh);   cudaGetSymbolAddress((void**)&kl, g_kl);
    cudaGetSymbolAddress((void**)&vth, g_vth); cudaGetSymbolAddress((void**)&vtl, g_vtl);
    cudaGetSymbolAddress((void**)&ch, g_ch);   cudaGetSymbolAddress((void**)&cl, g_cl);
    cudaGetSymbolAddress((void**)&attn_scratch, g_attn);

    float* attn = ((long)out_size >= OUT_TOTAL) ? (out + OUT0) : attn_scratch;

    cudaFuncSetAttribute(mma_gemm<0>, cudaFuncAttributeMaxDynamicSharedMemorySize, SM_PIPE);
    cudaFuncSetAttribute(mma_gemm<1>, cudaFuncAttributeMaxDynamicSharedMemorySize, SM_PIPE);
    cudaFuncSetAttribute(mma_gemm<4>, cudaFuncAttributeMaxDynamicSharedMemorySize, SM_PIPE);
    cudaFuncSetAttribute(fused_attn_k, cudaFuncAttributeMaxDynamicSharedMemorySize, FB_SM);

    // 0) One-launch split of all 7 fp32 inputs into bf16 hi/lo
    {
        SplitArgs a;
        a.x[0] = Q;  a.h[0] = Qh;  a.l[0] = Ql;  a.n4[0] = TOKENS * DMODEL / 4;
        a.x[1] = K;  a.h[1] = Kh;  a.l[1] = Kl;  a.n4[1] = TOKENS * DMODEL / 4;
        a.x[2] = V;  a.h[2] = Vh;  a.l[2] = Vl;  a.n4[2] = TOKENS * DMODEL / 4;
        a.x[3] = Wq; a.h[3] = Wqh; a.l[3] = Wql; a.n4[3] = DMODEL * DMODEL / 4;
        a.x[4] = Wk; a.h[4] = Wkh; a.l[4] = Wkl; a.n4[4] = DMODEL * DMODEL / 4;
        a.x[5] = Wv; a.h[5] = Wvh; a.l[5] = Wvl; a.n4[5] = DMODEL * DMODEL / 4;
        a.x[6] = Wo; a.h[6] = Woh; a.l[6] = Wol; a.n4[6] = DMODEL * DMODEL / 4;
        dim3 gs((TOKENS * DMODEL / 4 + 255) / 256, 7, 1);
        split_all<<<gs, 256>>>(a);
    }

    // 1-3) Projections (bf16 3-pass, pipelined); epilogues emit fp16 planes
    dim3 gp(DMODEL / NT, TOKENS / MT, 1);                       // (16, 32)
    mma_gemm<0><<<gp, 256, SM_PIPE>>>(Qh, Ql, Wqh, Wql, bq, nullptr, qh, ql,
                                      DMODEL, DMODEL, DMODEL);
    mma_gemm<0><<<gp, 256, SM_PIPE>>>(Kh, Kl, Wkh, Wkl, bk, nullptr, kh, kl,
                                      DMODEL, DMODEL, DMODEL);
    mma_gemm<1><<<gp, 256, SM_PIPE>>>(Vh, Vl, Wvh, Wvl, bv, nullptr, vth, vtl,
                                      DMODEL, DMODEL, DMODEL);

    // 4) Fused scores + softmax + context (fp16; cheap pass A, 2-pass O)
    dim3 gf(SEQ / 128, BH, 1);                                  // (16, 32)
    fused_attn_k<<<gf, 256, FB_SM>>>(qh, ql, kh, kl, vth, vtl, attn, ch, cl);

    // 5) Output projection: ctx @ Wo^T + bo -> out fp32 (bf16 3-pass)
    mma_gemm<4><<<gp, 256, SM_PIPE>>>(ch, cl, Woh, Wol, bo, out, nullptr, nullptr,
                                      DMODEL, DMODEL, DMODEL);

    (void)n_in; (void)in_sizes;
}

// round 12
// speedup vs baseline: 1.5363x; 1.0855x over previous
#include <cuda_runtime.h>
#include <cuda_bf16.h>
#include <cuda_fp16.h>
#include <cstdint>

// ---------------------------------------------------------------------------
// Problem constants
// ---------------------------------------------------------------------------
#define BATCH   2
#define SEQ     2048
#define DMODEL  1024
#define NHEAD   16
#define DK      64
#define BH      (BATCH * NHEAD)              // 32
#define TOKENS  (BATCH * SEQ)                // 4096
#define OUT0    (TOKENS * DMODEL)            // 4,194,304
#define ATTN_N  ((long)BH * SEQ * SEQ)       // 134,217,728
#define OUT_TOTAL (OUT0 + ATTN_N)

// ---------------------------------------------------------------------------
// Scratch (static device arrays; no cudaMalloc anywhere)
// ---------------------------------------------------------------------------
__device__ __nv_bfloat16 g_Qh[TOKENS * DMODEL], g_Ql[TOKENS * DMODEL];
__device__ __nv_bfloat16 g_Kh[TOKENS * DMODEL], g_Kl[TOKENS * DMODEL];
__device__ __nv_bfloat16 g_Vh[TOKENS * DMODEL], g_Vl[TOKENS * DMODEL];
__device__ __nv_bfloat16 g_Wqh[DMODEL * DMODEL], g_Wql[DMODEL * DMODEL];
__device__ __nv_bfloat16 g_Wkh[DMODEL * DMODEL], g_Wkl[DMODEL * DMODEL];
__device__ __nv_bfloat16 g_Wvh[DMODEL * DMODEL], g_Wvl[DMODEL * DMODEL];
__device__ __nv_bfloat16 g_Woh[DMODEL * DMODEL], g_Wol[DMODEL * DMODEL];
__device__ __half g_qh[TOKENS * DMODEL], g_ql[TOKENS * DMODEL];     // fp16
__device__ __half g_kh[TOKENS * DMODEL];                             // fp16 (hi only)
__device__ __half g_vth[BH * DK * SEQ], g_vtl[BH * DK * SEQ];        // fp16 V^T hi/lo
__device__ __nv_bfloat16 g_ch[TOKENS * DMODEL], g_cl[TOKENS * DMODEL];  // ctx bf16
__device__ float g_attn[ATTN_N];                 // fallback if d_out lacks attn

// ---------------------------------------------------------------------------
// Helpers
// ---------------------------------------------------------------------------
__device__ __forceinline__ uint32_t smem_u32(const void* p) {
    uint32_t a;
    asm("{ .reg .u64 t; cvta.to.shared.u64 t, %1; cvt.u32.u64 %0, t; }"
        : "=r"(a) : "l"(p));
    return a;
}
#define SWZ(off) ((off) ^ (((off) >> 3) & 0x70))

__device__ __forceinline__ void ldsm_x4(uint32_t& r0, uint32_t& r1,
                                        uint32_t& r2, uint32_t& r3, uint32_t a) {
    asm volatile("ldmatrix.sync.aligned.m8n8.x4.shared.b16 {%0,%1,%2,%3}, [%4];"
                 : "=r"(r0), "=r"(r1), "=r"(r2), "=r"(r3) : "r"(a));
}
__device__ __forceinline__ void mma_bf16(float* c, const uint32_t* a,
                                         uint32_t b0, uint32_t b1) {
    asm volatile(
        "mma.sync.aligned.m16n8k16.row.col.f32.bf16.bf16.f32 "
        "{%0,%1,%2,%3}, {%4,%5,%6,%7}, {%8,%9}, {%0,%1,%2,%3};"
        : "+f"(c[0]), "+f"(c[1]), "+f"(c[2]), "+f"(c[3])
        : "r"(a[0]), "r"(a[1]), "r"(a[2]), "r"(a[3]), "r"(b0), "r"(b1));
}
__device__ __forceinline__ void mma_f16(float* c, const uint32_t* a,
                                        uint32_t b0, uint32_t b1) {
    asm volatile(
        "mma.sync.aligned.m16n8k16.row.col.f32.f16.f16.f32 "
        "{%0,%1,%2,%3}, {%4,%5,%6,%7}, {%8,%9}, {%0,%1,%2,%3};"
        : "+f"(c[0]), "+f"(c[1]), "+f"(c[2]), "+f"(c[3])
        : "r"(a[0]), "r"(a[1]), "r"(a[2]), "r"(a[3]), "r"(b0), "r"(b1));
}
__device__ __forceinline__ void cp16(uint32_t dst, const void* src) {
    asm volatile("cp.async.cg.shared.global [%0], [%1], 16;"
                 :: "r"(dst), "l"(src) : "memory");
}
#define CP_COMMIT() asm volatile("cp.async.commit_group;" ::: "memory")
#define CP_WAIT1()  asm volatile("cp.async.wait_group 1;" ::: "memory")
#define CP_WAIT0()  asm volatile("cp.async.wait_group 0;" ::: "memory")

__device__ __forceinline__ uint32_t pack_half(float lo, float hi) {
    uint32_t r;
    asm("cvt.rn.f16x2.f32 %0, %1, %2;" : "=r"(r) : "f"(hi), "f"(lo));
    return r;
}

// ---------------------------------------------------------------------------
// One-launch fp32 -> bf16 hi/lo split over all 7 inputs (grid.y = segment)
// ---------------------------------------------------------------------------
struct SplitArgs {
    const float* x[7];
    __nv_bfloat16* h[7];
    __nv_bfloat16* l[7];
    int n4[7];
};

__global__ void __launch_bounds__(256)
split_all(SplitArgs a)
{
    const int seg = blockIdx.y;
    const int i = blockIdx.x * 256 + threadIdx.x;
    if (i >= a.n4[seg]) return;
    float4 v = ((const float4*)a.x[seg])[i];
    __nv_bfloat16 h0 = __float2bfloat16(v.x), h1 = __float2bfloat16(v.y);
    __nv_bfloat16 h2 = __float2bfloat16(v.z), h3 = __float2bfloat16(v.w);
    float l0 = v.x - __bfloat162float(h0), l1 = v.y - __bfloat162float(h1);
    float l2 = v.z - __bfloat162float(h2), l3 = v.w - __bfloat162float(h3);
    uint2 hv, lv;
    hv.x = (uint32_t)__bfloat16_as_ushort(h0) | ((uint32_t)__bfloat16_as_ushort(h1) << 16);
    hv.y = (uint32_t)__bfloat16_as_ushort(h2) | ((uint32_t)__bfloat16_as_ushort(h3) << 16);
    lv.x = (uint32_t)__bfloat16_as_ushort(__float2bfloat16(l0)) |
           ((uint32_t)__bfloat16_as_ushort(__float2bfloat16(l1)) << 16);
    lv.y = (uint32_t)__bfloat16_as_ushort(__float2bfloat16(l2)) |
           ((uint32_t)__bfloat16_as_ushort(__float2bfloat16(l3)) << 16);
    ((uint2*)a.h[seg])[i] = hv;
    ((uint2*)a.l[seg])[i] = lv;
}

// ---------------------------------------------------------------------------
// mma.sync split-bf16 GEMM (3-pass, pre-split operands, cp.async 2-stage).
// Tile M=128, N=64, K-tile=64; 256 threads.  C = A @ B^T.
// EPI 0: bias + fp16 hi/lo split store, ld 1024          [Q projection]
// EPI 1: bias + fp16 hi/lo split, transposed per-head    [V projection]
// EPI 2: bias + fp16 hi-only store, ld 1024              [K projection]
// EPI 4: bias + fp32 store, ld 1024                      [output projection]
// ---------------------------------------------------------------------------
#define MT 128
#define NT 64
#define KT 64
#define STG_STRIDE 49152
#define OFF_AH 0
#define OFF_AL 16384
#define OFF_BH 32768
#define OFF_BL 40960
#define SM_PIPE  98304

template <int EPI>
__global__ void __launch_bounds__(256)
mma_gemm(const __nv_bfloat16* __restrict__ Ah, const __nv_bfloat16* __restrict__ Al,
         const __nv_bfloat16* __restrict__ Bh, const __nv_bfloat16* __restrict__ Bl,
         const float* __restrict__ bias, float* __restrict__ outF,
         __half* __restrict__ outH, __half* __restrict__ outL,
         int K, int lda, int ldb)
{
    extern __shared__ uint8_t dsm[];
    const uint32_t sb = smem_u32(dsm);
    const int tid = threadIdx.x, wid = tid >> 5, lane = tid & 31;
    const int wm = wid >> 1, wn = wid & 1;
    const int n0 = blockIdx.x * NT, m0 = blockIdx.y * MT;

    float acc[2][4][4];
#pragma unroll
    for (int i = 0; i < 2; i++)
#pragma unroll
        for (int j = 0; j < 4; j++)
#pragma unroll
            for (int r = 0; r < 4; r++) acc[i][j][r] = 0.0f;

    const int lrow = lane & 15, lkh = lane >> 4;

    const int ntiles = K / KT;
    auto stage = [&](int kti, int buf) {
        const uint32_t b0 = sb + buf * STG_STRIDE;
        const int kt = kti * KT;
#pragma unroll
        for (int i = 0; i < 4; i++) {
            int chunk = tid + i * 256;
            int row = chunk >> 3, c16 = chunk & 7;
            long g = (long)(m0 + row) * lda + kt + c16 * 8;
            uint32_t so = SWZ((uint32_t)(row * 128 + c16 * 16));
            cp16(b0 + OFF_AH + so, Ah + g);
            cp16(b0 + OFF_AL + so, Al + g);
        }
#pragma unroll
        for (int i = 0; i < 2; i++) {
            int chunk = tid + i * 256;
            int row = chunk >> 3, c16 = chunk & 7;
            long g = (long)(n0 + row) * ldb + kt + c16 * 8;
            uint32_t so = SWZ((uint32_t)(row * 128 + c16 * 16));
            cp16(b0 + OFF_BH + so, Bh + g);
            cp16(b0 + OFF_BL + so, Bl + g);
        }
    };
    stage(0, 0);
    CP_COMMIT();
    for (int t = 0; t < ntiles; t++) {
        if (t + 1 < ntiles) { stage(t + 1, (t + 1) & 1); CP_COMMIT(); CP_WAIT1(); }
        else { CP_WAIT0(); }
        __syncthreads();
        const uint32_t b0 = sb + (t & 1) * STG_STRIDE;
#pragma unroll
        for (int ks = 0; ks < 4; ks++) {
            const uint32_t kb = ks * 32 + lkh * 16;
            uint32_t ah[2][4], al[2][4];
#pragma unroll
            for (int ms = 0; ms < 2; ms++) {
                uint32_t ro = (uint32_t)(wm * 32 + ms * 16 + lrow) * 128 + kb;
                ldsm_x4(ah[ms][0], ah[ms][1], ah[ms][2], ah[ms][3], b0 + OFF_AH + SWZ(ro));
                ldsm_x4(al[ms][0], al[ms][1], al[ms][2], al[ms][3], b0 + OFF_AL + SWZ(ro));
            }
            uint32_t bh[4][2], bl[4][2];
#pragma unroll
            for (int half = 0; half < 2; half++) {
                uint32_t ro = (uint32_t)(wn * 32 + half * 16 + lrow) * 128 + kb;
                uint32_t r0, r1, r2, r3;
                ldsm_x4(r0, r1, r2, r3, b0 + OFF_BH + SWZ(ro));
                bh[half * 2 + 0][0] = r0; bh[half * 2 + 0][1] = r2;
                bh[half * 2 + 1][0] = r1; bh[half * 2 + 1][1] = r3;
                ldsm_x4(r0, r1, r2, r3, b0 + OFF_BL + SWZ(ro));
                bl[half * 2 + 0][0] = r0; bl[half * 2 + 0][1] = r2;
                bl[half * 2 + 1][0] = r1; bl[half * 2 + 1][1] = r3;
            }
#pragma unroll
            for (int ms = 0; ms < 2; ms++)
#pragma unroll
                for (int nb = 0; nb < 4; nb++) {
                    mma_bf16(acc[ms][nb], ah[ms], bh[nb][0], bh[nb][1]);
                    mma_bf16(acc[ms][nb], al[ms], bh[nb][0], bh[nb][1]);
                    mma_bf16(acc[ms][nb], ah[ms], bl[nb][0], bl[nb][1]);
                }
        }
        __syncthreads();
    }

    // ---- epilogue: regs -> padded smem staging -> coalesced global ----
    float* st = (float*)dsm;                     // [128][65] fp32
    {
        const int lr = lane >> 2, lc = (lane & 3) * 2;
#pragma unroll
        for (int ms = 0; ms < 2; ms++)
#pragma unroll
            for (int nb = 0; nb < 4; nb++) {
                int r = wm * 32 + ms * 16 + lr;
                int c = wn * 32 + nb * 8 + lc;
                st[r * 65 + c]            = acc[ms][nb][0];
                st[r * 65 + c + 1]        = acc[ms][nb][1];
                st[(r + 8) * 65 + c]      = acc[ms][nb][2];
                st[(r + 8) * 65 + c + 1]  = acc[ms][nb][3];
            }
    }
    __syncthreads();

    if (EPI == 4) {            // OUT: fp32 + bias
        for (int i = tid; i < MT * NT; i += 256) {
            int row = i >> 6, c = i & 63;
            outF[(long)(m0 + row) * 1024 + n0 + c] = st[row * 65 + c] + bias[n0 + c];
        }
    } else if (EPI == 0) {     // Q: bias + fp16 hi/lo split
        for (int i = tid; i < MT * NT; i += 256) {
            int row = i >> 6, c = i & 63;
            float v = st[row * 65 + c] + bias[n0 + c];
            long o = (long)(m0 + row) * 1024 + n0 + c;
            __half h = __float2half_rn(v);
            outH[o] = h;
            outL[o] = __float2half_rn(v - __half2float(h));
        }
    } else if (EPI == 2) {     // K: bias + fp16 hi only
        for (int i = tid; i < MT * NT; i += 256) {
            int row = i >> 6, c = i & 63;
            float v = st[row * 65 + c] + bias[n0 + c];
            outH[(long)(m0 + row) * 1024 + n0 + c] = __float2half_rn(v);
        }
    } else {                   // V: bias + fp16 hi/lo, transposed [BH,64,S]
        for (int i = tid; i < MT * NT; i += 256) {
            int j = i >> 7, rl = i & 127;
            int r = m0 + rl, cg = n0 + j;
            float v = st[rl * 65 + j] + bias[cg];
            int b = r >> 11, s = r & 2047, hh = cg >> 6, jj = cg & 63;
            long o = ((long)(b * 16 + hh) * 64 + jj) * 2048 + s;
            __half h = __float2half_rn(v);
            outH[o] = h;
            outL[o] = __float2half_rn(v - __half2float(h));
        }
    }
    (void)outL;
}

// ---------------------------------------------------------------------------
// Fused scores + softmax + context — fp16.
// Pass A: S via qh*kh 1-pass -> row sums of exp.
// Pass B: S 2-pass (qh*kh + ql*kh; K=64 so dropped qh*kl term costs ~2.8e-4),
//         normalize, store attn once, P -> fp16 plane,
//         O += P @ (Vh + Vl) (2 MMA passes), cross-wn reduce, bf16 ctx store.
// Stage layout (24KB used of 32KB stride): KH+0, VH+8192, VL+16384.
// ---------------------------------------------------------------------------
#define FB_QH   0
#define FB_QL   16384
#define FB_ST0  32768
#define FB_STRIDE 32768
#define FB_PART 98304           // float[2][128]
#define FB_ROWL 99328           // float[128]
#define FB_SM   99840

__global__ void __launch_bounds__(256)
fused_attn_k(const __half* __restrict__ qh, const __half* __restrict__ ql,
             const __half* __restrict__ kh,
             const __half* __restrict__ vth, const __half* __restrict__ vtl,
             float* __restrict__ attn,
             __nv_bfloat16* __restrict__ ch, __nv_bfloat16* __restrict__ cl)
{
    extern __shared__ uint8_t dsm[];
    const uint32_t sb = smem_u32(dsm);
    const int tid = threadIdx.x, wid = tid >> 5, lane = tid & 31;
    const int wm = wid >> 1, wn = wid & 1;
    const int lrow = lane & 15, lkh = lane >> 4;
    const int lr = lane >> 2, lc = lane & 3;
    const int m0 = blockIdx.x * 128;
    const int z = blockIdx.y;
    const long base = (long)(z >> 4) * 2048L * 1024 + (long)(z & 15) * 64;
    const __half* qh_h = qh + base;
    const __half* ql_h = ql + base;
    const __half* kh_h = kh + base;
    const __half* vh_h = vth + (long)z * 64L * 2048;
    const __half* vl_h = vtl + (long)z * 64L * 2048;

    float* part  = (float*)(dsm + FB_PART);
    float* row_l = (float*)(dsm + FB_ROWL);

    auto stage_k_hi = [&](int t, int buf) {
        const uint32_t sd = sb + FB_ST0 + buf * FB_STRIDE;
#pragma unroll
        for (int i = 0; i < 2; i++) {
            int chunk = tid + i * 256;
            int row = chunk >> 3, c16 = chunk & 7;
            long g = (long)(t * 64 + row) * 1024 + c16 * 8;
            uint32_t so = SWZ((uint32_t)(row * 128 + c16 * 16));
            cp16(sd + so, kh_h + g);
        }
    };
    auto stage_kv = [&](int t, int buf) {
        const uint32_t sd = sb + FB_ST0 + buf * FB_STRIDE;
#pragma unroll
        for (int i = 0; i < 2; i++) {
            int chunk = tid + i * 256;
            int row = chunk >> 3, c16 = chunk & 7;
            long g = (long)(t * 64 + row) * 1024 + c16 * 8;
            uint32_t so = SWZ((uint32_t)(row * 128 + c16 * 16));
            cp16(sd + so, kh_h + g);
        }
#pragma unroll
        for (int i = 0; i < 2; i++) {
            int chunk = tid + i * 256;               // row = dk 0..63
            int row = chunk >> 3, c16 = chunk & 7;
            long g = (long)row * 2048 + t * 64 + c16 * 8;
            uint32_t so = SWZ((uint32_t)(row * 128 + c16 * 16));
            cp16(sd + 8192 + so, vh_h + g);
            cp16(sd + 16384 + so, vl_h + g);
        }
    };

    // S tile, 1-pass (pass A): qh * kh
    auto compute_tile_hi = [&](int buf, float acc[2][4][4]) {
#pragma unroll
        for (int i = 0; i < 2; i++)
#pragma unroll
            for (int j = 0; j < 4; j++)
#pragma unroll
                for (int r = 0; r < 4; r++) acc[i][j][r] = 0.0f;
        const uint32_t kbh = sb + FB_ST0 + buf * FB_STRIDE;
#pragma unroll
        for (int ks = 0; ks < 4; ks++) {
            const uint32_t kb = ks * 32 + lkh * 16;
            uint32_t ah[2][4];
#pragma unroll
            for (int ms = 0; ms < 2; ms++) {
                uint32_t ro = (uint32_t)(wm * 32 + ms * 16 + lrow) * 128 + kb;
                ldsm_x4(ah[ms][0], ah[ms][1], ah[ms][2], ah[ms][3], sb + FB_QH + SWZ(ro));
            }
            uint32_t bh[4][2];
#pragma unroll
            for (int half = 0; half < 2; half++) {
                uint32_t ro = (uint32_t)(wn * 32 + half * 16 + lrow) * 128 + kb;
                uint32_t r0, r1, r2, r3;
                ldsm_x4(r0, r1, r2, r3, kbh + SWZ(ro));
                bh[half * 2 + 0][0] = r0; bh[half * 2 + 0][1] = r2;
                bh[half * 2 + 1][0] = r1; bh[half * 2 + 1][1] = r3;
            }
#pragma unroll
            for (int ms = 0; ms < 2; ms++)
#pragma unroll
                for (int nb = 0; nb < 4; nb++)
                    mma_f16(acc[ms][nb], ah[ms], bh[nb][0], bh[nb][1]);
        }
    };
    // S tile, 2-pass (pass B): qh*kh + ql*kh
    auto compute_tile = [&](int buf, float acc[2][4][4]) {
#pragma unroll
        for (int i = 0; i < 2; i++)
#pragma unroll
            for (int j = 0; j < 4; j++)
#pragma unroll
                for (int r = 0; r < 4; r++) acc[i][j][r] = 0.0f;
        const uint32_t kbh = sb + FB_ST0 + buf * FB_STRIDE;
#pragma unroll
        for (int ks = 0; ks < 4; ks++) {
            const uint32_t kb = ks * 32 + lkh * 16;
            uint32_t ah[2][4], al[2][4];
#pragma unroll
            for (int ms = 0; ms < 2; ms++) {
                uint32_t ro = (uint32_t)(wm * 32 + ms * 16 + lrow) * 128 + kb;
                ldsm_x4(ah[ms][0], ah[ms][1], ah[ms][2], ah[ms][3], sb + FB_QH + SWZ(ro));
                ldsm_x4(al[ms][0], al[ms][1], al[ms][2], al[ms][3], sb + FB_QL + SWZ(ro));
            }
            uint32_t bh[4][2];
#pragma unroll
            for (int half = 0; half < 2; half++) {
                uint32_t ro = (uint32_t)(wn * 32 + half * 16 + lrow) * 128 + kb;
                uint32_t r0, r1, r2, r3;
                ldsm_x4(r0, r1, r2, r3, kbh + SWZ(ro));
                bh[half * 2 + 0][0] = r0; bh[half * 2 + 0][1] = r2;
                bh[half * 2 + 1][0] = r1; bh[half * 2 + 1][1] = r3;
            }
#pragma unroll
            for (int ms = 0; ms < 2; ms++)
#pragma unroll
                for (int nb = 0; nb < 4; nb++) {
                    mma_f16(acc[ms][nb], ah[ms], bh[nb][0], bh[nb][1]);
                    mma_f16(acc[ms][nb], al[ms], bh[nb][0], bh[nb][1]);
                }
        }
    };

    // ---- prologue: q tile + k tile 0 ----
#pragma unroll
    for (int i = 0; i < 4; i++) {
        int chunk = tid + i * 256;
        int row = chunk >> 3, c16 = chunk & 7;
        long g = (long)(m0 + row) * 1024 + c16 * 8;
        uint32_t so = SWZ((uint32_t)(row * 128 + c16 * 16));
        cp16(sb + FB_QH + so, qh_h + g);
        cp16(sb + FB_QL + so, ql_h + g);
    }
    if (tid < 128) row_l[tid] = 0.0f;
    stage_k_hi(0, 0);
    CP_COMMIT();

    float acc[2][4][4];

    // ---- pass A: approximate S (fp16 hi*hi), row sums of exp ----
    for (int t = 0; t < 32; t++) {
        if (t + 1 < 32) { stage_k_hi(t + 1, (t + 1) & 1); CP_COMMIT(); CP_WAIT1(); }
        else { CP_WAIT0(); }
        __syncthreads();
        compute_tile_hi(t & 1, acc);
#pragma unroll
        for (int ms = 0; ms < 2; ms++) {
            float s0 = 0.0f, s1 = 0.0f;
#pragma unroll
            for (int nb = 0; nb < 4; nb++) {
                s0 += __expf(acc[ms][nb][0] * 0.125f) + __expf(acc[ms][nb][1] * 0.125f);
                s1 += __expf(acc[ms][nb][2] * 0.125f) + __expf(acc[ms][nb][3] * 0.125f);
            }
            s0 += __shfl_xor_sync(0xffffffffu, s0, 1);
            s0 += __shfl_xor_sync(0xffffffffu, s0, 2);
            s1 += __shfl_xor_sync(0xffffffffu, s1, 1);
            s1 += __shfl_xor_sync(0xffffffffu, s1, 2);
            if (lc == 0) {
                part[wn * 128 + wm * 32 + ms * 16 + lr]     = s0;
                part[wn * 128 + wm * 32 + ms * 16 + 8 + lr] = s1;
            }
        }
        __syncthreads();
        if (tid < 128) row_l[tid] += part[tid] + part[128 + tid];
    }
    __syncthreads();
    float inv[2][2];
#pragma unroll
    for (int ms = 0; ms < 2; ms++) {
        inv[ms][0] = 1.0f / row_l[wm * 32 + ms * 16 + lr];
        inv[ms][1] = 1.0f / row_l[wm * 32 + ms * 16 + 8 + lr];
    }

    float accO[2][8][4];
#pragma unroll
    for (int ms = 0; ms < 2; ms++)
#pragma unroll
        for (int dn = 0; dn < 8; dn++)
#pragma unroll
            for (int r = 0; r < 4; r++) accO[ms][dn][r] = 0.0f;

    // ---- pass B: 2-pass S, normalize, store attn, O += P @ (Vh + Vl) ----
    stage_kv(0, 0);
    CP_COMMIT();
    for (int t = 0; t < 32; t++) {
        if (t + 1 < 32) { stage_kv(t + 1, (t + 1) & 1); CP_COMMIT(); CP_WAIT1(); }
        else { CP_WAIT0(); }
        __syncthreads();
        compute_tile(t & 1, acc);

#pragma unroll
        for (int ms = 0; ms < 2; ms++)
#pragma unroll
            for (int nb = 0; nb < 4; nb++) {
                acc[ms][nb][0] = __expf(acc[ms][nb][0] * 0.125f) * inv[ms][0];
                acc[ms][nb][1] = __expf(acc[ms][nb][1] * 0.125f) * inv[ms][0];
                acc[ms][nb][2] = __expf(acc[ms][nb][2] * 0.125f) * inv[ms][1];
                acc[ms][nb][3] = __expf(acc[ms][nb][3] * 0.125f) * inv[ms][1];
            }

        const int colb = t * 64 + wn * 32 + lc * 2;
#pragma unroll
        for (int ms = 0; ms < 2; ms++) {
            long rb0 = ((long)z * 2048 + m0 + wm * 32 + ms * 16 + lr) * 2048;
            long rb1 = rb0 + 8L * 2048;
#pragma unroll
            for (int nb = 0; nb < 4; nb++) {
                *(float2*)(attn + rb0 + colb + nb * 8) =
                    make_float2(acc[ms][nb][0], acc[ms][nb][1]);
                *(float2*)(attn + rb1 + colb + nb * 8) =
                    make_float2(acc[ms][nb][2], acc[ms][nb][3]);
            }
        }

        // O += P @ (Vh + Vl)
        const uint32_t vbh = sb + FB_ST0 + (t & 1) * FB_STRIDE + 8192;
        const uint32_t vbl = vbh + 8192;
#pragma unroll
        for (int kh2 = 0; kh2 < 2; kh2++) {
            uint32_t vh[8][2], vl[8][2];
#pragma unroll
            for (int dh = 0; dh < 4; dh++) {
                uint32_t ro = (uint32_t)(dh * 16 + lrow) * 128 +
                              (uint32_t)(wn * 32 + kh2 * 16) * 2 + lkh * 16;
                uint32_t r0, r1, r2, r3;
                ldsm_x4(r0, r1, r2, r3, vbh + SWZ(ro));
                vh[dh * 2 + 0][0] = r0; vh[dh * 2 + 0][1] = r2;
                vh[dh * 2 + 1][0] = r1; vh[dh * 2 + 1][1] = r3;
                ldsm_x4(r0, r1, r2, r3, vbl + SWZ(ro));
                vl[dh * 2 + 0][0] = r0; vl[dh * 2 + 0][1] = r2;
                vl[dh * 2 + 1][0] = r1; vl[dh * 2 + 1][1] = r3;
            }
#pragma unroll
            for (int ms = 0; ms < 2; ms++) {
                const float* c0 = acc[ms][2 * kh2];
                const float* c1 = acc[ms][2 * kh2 + 1];
                uint32_t ph[4];
                ph[0] = pack_half(c0[0], c0[1]);
                ph[1] = pack_half(c0[2], c0[3]);
                ph[2] = pack_half(c1[0], c1[1]);
                ph[3] = pack_half(c1[2], c1[3]);
#pragma unroll
                for (int dn = 0; dn < 8; dn++) {
                    mma_f16(accO[ms][dn], ph, vh[dn][0], vh[dn][1]);
                    mma_f16(accO[ms][dn], ph, vl[dn][0], vl[dn][1]);
                }
            }
        }
        __syncthreads();
    }

    // ---- ctx epilogue: cross-wn reduce in smem, bf16 split store [B,S,D] ----
    float* st = (float*)dsm;
    {
        const int lc2 = lc * 2;
        if (wn == 0) {
#pragma unroll
            for (int ms = 0; ms < 2; ms++)
#pragma unroll
                for (int dn = 0; dn < 8; dn++) {
                    int r = wm * 32 + ms * 16 + lr;
                    int c = dn * 8 + lc2;
                    st[r * 65 + c]           = accO[ms][dn][0];
                    st[r * 65 + c + 1]       = accO[ms][dn][1];
                    st[(r + 8) * 65 + c]     = accO[ms][dn][2];
                    st[(r + 8) * 65 + c + 1] = accO[ms][dn][3];
                }
        }
        __syncthreads();
        if (wn == 1) {
#pragma unroll
            for (int ms = 0; ms < 2; ms++)
#pragma unroll
                for (int dn = 0; dn < 8; dn++) {
                    int r = wm * 32 + ms * 16 + lr;
                    int c = dn * 8 + lc2;
                    st[r * 65 + c]           += accO[ms][dn][0];
                    st[r * 65 + c + 1]       += accO[ms][dn][1];
                    st[(r + 8) * 65 + c]     += accO[ms][dn][2];
                    st[(r + 8) * 65 + c + 1] += accO[ms][dn][3];
                }
        }
        __syncthreads();
    }
    {
        const int b = z >> 4, hh = z & 15;
        for (int i = tid; i < 128 * 64; i += 256) {
            int row = i >> 6, c = i & 63;
            float v = st[row * 65 + c];
            long o = (long)((b << 11) + m0 + row) * 1024 + hh * 64 + c;
            __nv_bfloat16 h = __float2bfloat16(v);
            ch[o] = h;
            cl[o] = __float2bfloat16(v - __bfloat162float(h));
        }
    }
}

// ---------------------------------------------------------------------------
extern "C" void kernel_launch(void* const* d_in, const int* in_sizes, int n_in,
                              void* d_out, int out_size)
{
    const float* Q  = (const float*)d_in[0];
    const float* K  = (const float*)d_in[1];
    const float* V  = (const float*)d_in[2];
    const float* Wq = (const float*)d_in[3];
    const float* bq = (const float*)d_in[4];
    const float* Wk = (const float*)d_in[5];
    const float* bk = (const float*)d_in[6];
    const float* Wv = (const float*)d_in[7];
    const float* bv = (const float*)d_in[8];
    const float* Wo = (const float*)d_in[9];
    const float* bo = (const float*)d_in[10];
    float* out = (float*)d_out;

    __nv_bfloat16 *Qh, *Ql, *Kh, *Kl, *Vh, *Vl;
    __nv_bfloat16 *Wqh, *Wql, *Wkh, *Wkl, *Wvh, *Wvl, *Woh, *Wol;
    __half *qh, *ql, *kh, *vth, *vtl;
    __nv_bfloat16 *ch, *cl;
    float* attn_scratch;
    cudaGetSymbolAddress((void**)&Qh, g_Qh);   cudaGetSymbolAddress((void**)&Ql, g_Ql);
    cudaGetSymbolAddress((void**)&Kh, g_Kh);   cudaGetSymbolAddress((void**)&Kl, g_Kl);
    cudaGetSymbolAddress((void**)&Vh, g_Vh);   cudaGetSymbolAddress((void**)&Vl, g_Vl);
    cudaGetSymbolAddress((void**)&Wqh, g_Wqh); cudaGetSymbolAddress((void**)&Wql, g_Wql);
    cudaGetSymbolAddress((void**)&Wkh, g_Wkh); cudaGetSymbolAddress((void**)&Wkl, g_Wkl);
    cudaGetSymbolAddress((void**)&Wvh, g_Wvh); cudaGetSymbolAddress((void**)&Wvl, g_Wvl);
    cudaGetSymbolAddress((void**)&Woh, g_Woh); cudaGetSymbolAddress((void**)&Wol, g_Wol);
    cudaGetSymbolAddress((void**)&qh, g_qh);   cudaGetSymbolAddress((void**)&ql, g_ql);
    cudaGetSymbolAddress((void**)&kh, g_kh);
    cudaGetSymbolAddress((void**)&vth, g_vth); cudaGetSymbolAddress((void**)&vtl, g_vtl);
    cudaGetSymbolAddress((void**)&ch, g_ch);   cudaGetSymbolAddress((void**)&cl, g_cl);
    cudaGetSymbolAddress((void**)&attn_scratch, g_attn);

    float* attn = ((long)out_size >= OUT_TOTAL) ? (out + OUT0) : attn_scratch;

    cudaFuncSetAttribute(mma_gemm<0>, cudaFuncAttributeMaxDynamicSharedMemorySize, SM_PIPE);
    cudaFuncSetAttribute(mma_gemm<1>, cudaFuncAttributeMaxDynamicSharedMemorySize, SM_PIPE);
    cudaFuncSetAttribute(mma_gemm<2>, cudaFuncAttributeMaxDynamicSharedMemorySize, SM_PIPE);
    cudaFuncSetAttribute(mma_gemm<4>, cudaFuncAttributeMaxDynamicSharedMemorySize, SM_PIPE);
    cudaFuncSetAttribute(fused_attn_k, cudaFuncAttributeMaxDynamicSharedMemorySize, FB_SM);

    // 0) One-launch split of all 7 fp32 inputs into bf16 hi/lo
    {
        SplitArgs a;
        a.x[0] = Q;  a.h[0] = Qh;  a.l[0] = Ql;  a.n4[0] = TOKENS * DMODEL / 4;
        a.x[1] = K;  a.h[1] = Kh;  a.l[1] = Kl;  a.n4[1] = TOKENS * DMODEL / 4;
        a.x[2] = V;  a.h[2] = Vh;  a.l[2] = Vl;  a.n4[2] = TOKENS * DMODEL / 4;
        a.x[3] = Wq; a.h[3] = Wqh; a.l[3] = Wql; a.n4[3] = DMODEL * DMODEL / 4;
        a.x[4] = Wk; a.h[4] = Wkh; a.l[4] = Wkl; a.n4[4] = DMODEL * DMODEL / 4;
        a.x[5] = Wv; a.h[5] = Wvh; a.l[5] = Wvl; a.n4[5] = DMODEL * DMODEL / 4;
        a.x[6] = Wo; a.h[6] = Woh; a.l[6] = Wol; a.n4[6] = DMODEL * DMODEL / 4;
        dim3 gs((TOKENS * DMODEL / 4 + 255) / 256, 7, 1);
        split_all<<<gs, 256>>>(a);
    }

    // 1-3) Projections (bf16 3-pass): Q -> fp16 hi/lo, K -> fp16 hi, V -> hi/lo^T
    dim3 gp(DMODEL / NT, TOKENS / MT, 1);                       // (16, 32)
    mma_gemm<0><<<gp, 256, SM_PIPE>>>(Qh, Ql, Wqh, Wql, bq, nullptr, qh, ql,
                                      DMODEL, DMODEL, DMODEL);
    mma_gemm<2><<<gp, 256, SM_PIPE>>>(Kh, Kl, Wkh, Wkl, bk, nullptr, kh, nullptr,
                                      DMODEL, DMODEL, DMODEL);
    mma_gemm<1><<<gp, 256, SM_PIPE>>>(Vh, Vl, Wvh, Wvl, bv, nullptr, vth, vtl,
                                      DMODEL, DMODEL, DMODEL);

    // 4) Fused scores + softmax + context (2-pass S, 2-pass O)
    dim3 gf(SEQ / 128, BH, 1);                                  // (16, 32)
    fused_attn_k<<<gf, 256, FB_SM>>>(qh, ql, kh, vth, vtl, attn, ch, cl);

    // 5) Output projection: ctx @ Wo^T + bo -> out fp32 (bf16 3-pass)
    mma_gemm<4><<<gp, 256, SM_PIPE>>>(ch, cl, Woh, Wol, bo, out, nullptr, nullptr,
                                      DMODEL, DMODEL, DMODEL);

    (void)n_in; (void)in_sizes;
}